// round 1
// baseline (speedup 1.0000x reference)
#include <cuda_runtime.h>
#include <cuda_bf16.h>

#define SPD   48
#define VOX   (48*48*48)      /* 110592 */
#define CH    96
#define CH4   384
#define LATD  8
#define STY   128
#define NB    2

/* ---------------- scratch (device globals; no allocation) ---------------- */
__device__ float g_wdw[NB * CH * 343];
__device__ float g_bdw[NB * CH];
__device__ float g_W1[NB * CH4 * CH];
__device__ float g_b1[NB * CH4];
__device__ float g_W2[NB * CH * CH4];
__device__ float g_b2[NB * CH];
__device__ float g_h[(size_t)NB * CH * VOX];                 /* dwconv out, [b][c][v] fp32 */
__device__ __nv_bfloat16 g_hn[(size_t)NB * VOX * CH];        /* LN out, [b][v][c] bf16     */
__device__ __nv_bfloat16 g_y1[(size_t)NB * VOX * CH4];       /* gelu(pw1) [b][v][4c] bf16  */

/* ---------------- helpers ---------------- */
__device__ __forceinline__ unsigned long long pack2(float lo, float hi) {
    unsigned long long r;
    asm("mov.b64 %0, {%1, %2};" : "=l"(r) : "f"(lo), "f"(hi));
    return r;
}
__device__ __forceinline__ void unpack2(unsigned long long v, float& lo, float& hi) {
    asm("mov.b64 {%0, %1}, %2;" : "=f"(lo), "=f"(hi) : "l"(v));
}
__device__ __forceinline__ void fma2(unsigned long long& d, unsigned long long a, unsigned long long b) {
    asm("fma.rn.f32x2 %0, %1, %2, %0;" : "+l"(d) : "l"(a), "l"(b));
}
__device__ __forceinline__ float gelu_exact(float x) {
    return 0.5f * x * (1.0f + erff(x * 0.7071067811865475f));
}

/* ---------------- K0: hyper-weight materialization ---------------- */
__global__ void k_weights(const float* __restrict__ s,
    const float* __restrict__ dw_fc_w,  const float* __restrict__ dw_fc_b,
    const float* __restrict__ dw_bank,  const float* __restrict__ dw_bias_bank,
    const float* __restrict__ pw1_fc_w, const float* __restrict__ pw1_fc_b,
    const float* __restrict__ pw1_bank, const float* __restrict__ pw1_bias_bank,
    const float* __restrict__ pw2_fc_w, const float* __restrict__ pw2_fc_b,
    const float* __restrict__ pw2_bank, const float* __restrict__ pw2_bias_bank)
{
    const int stage = blockIdx.y;
    const int b = blockIdx.z;
    __shared__ float z[LATD];
    const float* fcw = (stage == 0) ? dw_fc_w : (stage == 1) ? pw1_fc_w : pw2_fc_w;
    const float* fcb = (stage == 0) ? dw_fc_b : (stage == 1) ? pw1_fc_b : pw2_fc_b;
    if (threadIdx.x < LATD) {
        float acc = fcb[threadIdx.x];
        for (int j = 0; j < STY; j++) acc += s[b * STY + j] * fcw[threadIdx.x * STY + j];
        z[threadIdx.x] = acc;
    }
    __syncthreads();
    const int idx = blockIdx.x * blockDim.x + threadIdx.x;
    if (stage == 0) {
        const int NW = CH * 343;
        if (idx < NW) {
            float a = 0.f;
            #pragma unroll
            for (int l = 0; l < LATD; l++) a += dw_bank[(size_t)idx * LATD + l] * z[l];
            g_wdw[b * NW + idx] = a;
        } else if (idx < NW + CH) {
            const int c = idx - NW; float a = 0.f;
            #pragma unroll
            for (int l = 0; l < LATD; l++) a += dw_bias_bank[c * LATD + l] * z[l];
            g_bdw[b * CH + c] = a;
        }
    } else if (stage == 1) {
        const int NW = CH4 * CH;
        if (idx < NW) {
            float a = 0.f;
            #pragma unroll
            for (int l = 0; l < LATD; l++) a += pw1_bank[(size_t)idx * LATD + l] * z[l];
            g_W1[b * NW + idx] = a;
        } else if (idx < NW + CH4) {
            const int o = idx - NW; float a = 0.f;
            #pragma unroll
            for (int l = 0; l < LATD; l++) a += pw1_bias_bank[o * LATD + l] * z[l];
            g_b1[b * CH4 + o] = a;
        }
    } else {
        const int NW = CH * CH4;
        if (idx < NW) {
            float a = 0.f;
            #pragma unroll
            for (int l = 0; l < LATD; l++) a += pw2_bank[(size_t)idx * LATD + l] * z[l];
            g_W2[b * NW + idx] = a;
        } else if (idx < NW + CH) {
            const int o = idx - NW; float a = 0.f;
            #pragma unroll
            for (int l = 0; l < LATD; l++) a += pw2_bias_bank[o * LATD + l] * z[l];
            g_b2[b * CH + o] = a;
        }
    }
}

/* ---------------- K1: depthwise 7^3 conv (pad 3), fp32 ----------------
   Block: one (b,c), tile 4(d) x 8(h) x 48(w). 192 threads, each 8 outputs along w. */
__global__ __launch_bounds__(192) void k_dwconv(const float* __restrict__ x)
{
    const int tile = blockIdx.x;            /* 0..71: 12 d-tiles x 6 h-tiles */
    const int c = blockIdx.y, b = blockIdx.z;
    const int d_t = tile / 6, h_t = tile % 6;

    __shared__ __align__(16) float sm[10 * 14 * 56];
    __shared__ float wgt[343];
    __shared__ float sbias;

    const float* xin = x + (size_t)(b * CH + c) * VOX;
    for (int i = threadIdx.x; i < 343; i += 192) wgt[i] = g_wdw[(b * CH + c) * 343 + i];
    if (threadIdx.x == 0) sbias = g_bdw[b * CH + c];

    const int d0 = d_t * 4 - 3, h0 = h_t * 8 - 3;
    for (int i = threadIdx.x; i < 10 * 14 * 56; i += 192) {
        const int dd = i / (14 * 56);
        const int r  = i - dd * (14 * 56);
        const int hh = r / 56;
        const int ww = r - hh * 56;
        const int gd = d0 + dd, gh = h0 + hh, gw = ww - 3;
        float v = 0.f;
        if ((unsigned)gd < 48u && (unsigned)gh < 48u && (unsigned)gw < 48u)
            v = xin[gd * 2304 + gh * 48 + gw];
        sm[i] = v;
    }
    __syncthreads();

    const int wseg = threadIdx.x % 6;
    const int dh   = threadIdx.x / 6;       /* 0..31 */
    const int ld = dh >> 3, lh = dh & 7;
    const int w0 = wseg * 8;

    float acc[8];
    #pragma unroll
    for (int i = 0; i < 8; i++) acc[i] = 0.f;

    #pragma unroll 1
    for (int kd = 0; kd < 7; kd++) {
        #pragma unroll
        for (int kh = 0; kh < 7; kh++) {
            const float* row = &sm[(ld + kd) * 784 + (lh + kh) * 56 + w0];
            float r[16];
            *(float4*)&r[0]  = *(const float4*)&row[0];
            *(float4*)&r[4]  = *(const float4*)&row[4];
            *(float4*)&r[8]  = *(const float4*)&row[8];
            *(float4*)&r[12] = *(const float4*)&row[12];
            const float* wp = &wgt[kd * 49 + kh * 7];
            #pragma unroll
            for (int kw = 0; kw < 7; kw++) {
                const float wv = wp[kw];
                #pragma unroll
                for (int i = 0; i < 8; i++) acc[i] = fmaf(wv, r[i + kw], acc[i]);
            }
        }
    }

    const int gd = d_t * 4 + ld, gh = h_t * 8 + lh;
    float* outp = g_h + (size_t)(b * CH + c) * VOX + gd * 2304 + gh * 48 + w0;
    const float bsv = sbias;
    #pragma unroll
    for (int i = 0; i < 8; i++) acc[i] += bsv;
    *(float4*)&outp[0] = make_float4(acc[0], acc[1], acc[2], acc[3]);
    *(float4*)&outp[4] = make_float4(acc[4], acc[5], acc[6], acc[7]);
}

/* ---------------- K2: channel LayerNorm + transpose to [v][c] bf16 ---------------- */
__global__ __launch_bounds__(256) void k_ln(const float* __restrict__ ln_w,
                                            const float* __restrict__ ln_b)
{
    const int b = blockIdx.y;
    const int v0 = blockIdx.x * 64;
    __shared__ float sm[96 * 65];
    __shared__ float ps[256], ps2[256];
    __shared__ float smean[64], srstd[64];

    const float* hin = g_h + (size_t)b * CH * VOX;
    for (int i = threadIdx.x; i < 96 * 64; i += 256) {
        const int cc = i >> 6, vv = i & 63;
        sm[cc * 65 + vv] = hin[(size_t)cc * VOX + v0 + vv];
    }
    __syncthreads();
    {
        const int vv = threadIdx.x & 63, q = threadIdx.x >> 6;
        float s1 = 0.f, s2 = 0.f;
        for (int cc = q * 24; cc < q * 24 + 24; cc++) {
            const float t = sm[cc * 65 + vv]; s1 += t; s2 += t * t;
        }
        ps[threadIdx.x] = s1; ps2[threadIdx.x] = s2;
    }
    __syncthreads();
    if (threadIdx.x < 64) {
        const float s1 = ps[threadIdx.x] + ps[threadIdx.x + 64] + ps[threadIdx.x + 128] + ps[threadIdx.x + 192];
        const float s2 = ps2[threadIdx.x] + ps2[threadIdx.x + 64] + ps2[threadIdx.x + 128] + ps2[threadIdx.x + 192];
        const float mean = s1 * (1.f / 96.f);
        const float var  = s2 * (1.f / 96.f) - mean * mean;
        smean[threadIdx.x] = mean;
        srstd[threadIdx.x] = rsqrtf(var + 1e-6f);
    }
    __syncthreads();
    __nv_bfloat16* outp = g_hn + (size_t)b * VOX * CH;
    for (int i = threadIdx.x; i < 64 * 48; i += 256) {
        const int vv = i / 48;
        const int cp = i - vv * 48;
        const int c0 = cp * 2;
        const float mean = smean[vv], rs = srstd[vv];
        const float a0 = (sm[c0 * 65 + vv]       - mean) * rs * ln_w[c0]     + ln_b[c0];
        const float a1 = (sm[(c0 + 1) * 65 + vv] - mean) * rs * ln_w[c0 + 1] + ln_b[c0 + 1];
        *(__nv_bfloat162*)(outp + (size_t)(v0 + vv) * CH + c0) = __floats2bfloat162_rn(a0, a1);
    }
}

/* ---------------- K3: pw1 GEMM (K=96) + bias + exact GELU -> bf16 ----------------
   Block tile 128(v) x 64(o). 256 threads; micro 8M x 4N via f32x2. M slots: tx+16*i. */
__global__ __launch_bounds__(256) void k_gemm1()
{
    const int nb = blockIdx.x * 64;
    const int vb = blockIdx.y * 128;
    const int b  = blockIdx.z;
    const __nv_bfloat16* A = g_hn + (size_t)b * VOX * CH;
    const float* Bw = g_W1 + b * CH4 * CH;

    __shared__ __align__(16) float As[16 * 128];
    __shared__ float Bs[16 * 64];
    __shared__ float Cs[128 * 65];

    unsigned long long acc[4][4];
    #pragma unroll
    for (int i = 0; i < 4; i++)
        #pragma unroll
        for (int j = 0; j < 4; j++) acc[i][j] = 0ull;

    const int tx = threadIdx.x & 15, ty = threadIdx.x >> 4;
    const int n0 = ty * 4;
    const int lm = threadIdx.x & 127, lsA = threadIdx.x >> 7;
    const int lo = threadIdx.x & 63,  lsB = threadIdx.x >> 6;

    for (int k0 = 0; k0 < 96; k0 += 16) {
        const uint4 av = *(const uint4*)(A + (size_t)(vb + lm) * CH + k0 + lsA * 8);
        const unsigned* u = (const unsigned*)&av;
        #pragma unroll
        for (int j = 0; j < 4; j++) {
            const float2 f = __bfloat1622float2(*(const __nv_bfloat162*)&u[j]);
            As[(lsA * 8 + 2 * j) * 128 + lm]     = f.x;
            As[(lsA * 8 + 2 * j + 1) * 128 + lm] = f.y;
        }
        const float4 bv = *(const float4*)(Bw + (nb + lo) * CH + k0 + lsB * 4);
        Bs[(lsB * 4 + 0) * 64 + lo] = bv.x;
        Bs[(lsB * 4 + 1) * 64 + lo] = bv.y;
        Bs[(lsB * 4 + 2) * 64 + lo] = bv.z;
        Bs[(lsB * 4 + 3) * 64 + lo] = bv.w;
        __syncthreads();
        #pragma unroll
        for (int k = 0; k < 16; k++) {
            float a[8];
            #pragma unroll
            for (int i = 0; i < 8; i++) a[i] = As[k * 128 + tx + 16 * i];
            unsigned long long a2[4];
            #pragma unroll
            for (int j = 0; j < 4; j++) a2[j] = pack2(a[2 * j], a[2 * j + 1]);
            #pragma unroll
            for (int j = 0; j < 4; j++) {
                const float bvv = Bs[k * 64 + n0 + j];
                const unsigned long long b2 = pack2(bvv, bvv);
                fma2(acc[0][j], a2[0], b2);
                fma2(acc[1][j], a2[1], b2);
                fma2(acc[2][j], a2[2], b2);
                fma2(acc[3][j], a2[3], b2);
            }
        }
        __syncthreads();
    }

    float biasj[4];
    #pragma unroll
    for (int j = 0; j < 4; j++) biasj[j] = g_b1[b * CH4 + nb + n0 + j];

    #pragma unroll
    for (int i = 0; i < 4; i++) {
        #pragma unroll
        for (int j = 0; j < 4; j++) {
            float lof, hif; unpack2(acc[i][j], lof, hif);
            const int mA = tx + 16 * (2 * i);
            const int mB = tx + 16 * (2 * i + 1);
            Cs[mA * 65 + n0 + j] = gelu_exact(lof + biasj[j]);
            Cs[mB * 65 + n0 + j] = gelu_exact(hif + biasj[j]);
        }
    }
    __syncthreads();

    __nv_bfloat16* Y = g_y1 + (size_t)b * VOX * CH4;
    for (int i = threadIdx.x; i < 128 * 8; i += 256) {
        const int m = i >> 3, ch = i & 7;
        unsigned uw[4];
        #pragma unroll
        for (int j = 0; j < 4; j++) {
            const __nv_bfloat162 p = __floats2bfloat162_rn(Cs[m * 65 + ch * 8 + 2 * j],
                                                           Cs[m * 65 + ch * 8 + 2 * j + 1]);
            uw[j] = *(const unsigned*)&p;
        }
        *(uint4*)(Y + (size_t)(vb + m) * CH4 + nb + ch * 8) = make_uint4(uw[0], uw[1], uw[2], uw[3]);
    }
}

/* ---------------- K4: pw2 GEMM (K=384) + bias + residual (x + gamma*h) ----------------
   Block tile 64(v) x 96(o). 256 threads; micro 4M x 6N via f32x2. */
__global__ __launch_bounds__(256) void k_gemm2(const float* __restrict__ x,
                                               const float* __restrict__ gamma,
                                               float* __restrict__ outg)
{
    const int vb = blockIdx.x * 64;
    const int b  = blockIdx.y;
    const __nv_bfloat16* A = g_y1 + (size_t)b * VOX * CH4;
    const float* Bw = g_W2 + b * CH * CH4;

    __shared__ __align__(16) float As[16 * 64];
    __shared__ float Bs[16 * 97];
    __shared__ float Cs[96 * 65];

    unsigned long long acc[2][6];
    #pragma unroll
    for (int i = 0; i < 2; i++)
        #pragma unroll
        for (int j = 0; j < 6; j++) acc[i][j] = 0ull;

    const int tx = threadIdx.x & 15, ty = threadIdx.x >> 4;
    const int n0 = tx * 6, m0 = ty * 4;
    const int lm = threadIdx.x & 63, lsA = threadIdx.x >> 6;   /* 0..3 */

    for (int k0 = 0; k0 < CH4; k0 += 16) {
        const unsigned long long av =
            *(const unsigned long long*)(A + (size_t)(vb + lm) * CH4 + k0 + lsA * 4);
        const unsigned* u = (const unsigned*)&av;
        #pragma unroll
        for (int j = 0; j < 2; j++) {
            const float2 f = __bfloat1622float2(*(const __nv_bfloat162*)&u[j]);
            As[(lsA * 4 + 2 * j) * 64 + lm]     = f.x;
            As[(lsA * 4 + 2 * j + 1) * 64 + lm] = f.y;
        }
        for (int i = threadIdx.x; i < 96 * 16; i += 256) {
            const int o = i >> 4, kk = i & 15;
            Bs[kk * 97 + o] = Bw[o * CH4 + k0 + kk];
        }
        __syncthreads();
        #pragma unroll
        for (int k = 0; k < 16; k++) {
            const unsigned long long* pa = (const unsigned long long*)&As[k * 64 + m0];
            const unsigned long long a0 = pa[0], a1 = pa[1];
            #pragma unroll
            for (int j = 0; j < 6; j++) {
                const float bvv = Bs[k * 97 + n0 + j];
                const unsigned long long b2 = pack2(bvv, bvv);
                fma2(acc[0][j], a0, b2);
                fma2(acc[1][j], a1, b2);
            }
        }
        __syncthreads();
    }

    #pragma unroll
    for (int j = 0; j < 6; j++) {
        const int o = n0 + j;
        const float bias = g_b2[b * CH + o];
        #pragma unroll
        for (int i = 0; i < 2; i++) {
            float lof, hif; unpack2(acc[i][j], lof, hif);
            Cs[o * 65 + m0 + 2 * i]     = lof + bias;
            Cs[o * 65 + m0 + 2 * i + 1] = hif + bias;
        }
    }
    __syncthreads();

    for (int i = threadIdx.x; i < 96 * 16; i += 256) {
        const int o = i >> 4, sg = i & 15;
        const size_t oidx = (size_t)(b * CH + o) * VOX + vb + sg * 4;
        const float g = gamma[o];
        const float4 xv = *(const float4*)(x + oidx);
        float4 res;
        res.x = xv.x + g * Cs[o * 65 + sg * 4 + 0];
        res.y = xv.y + g * Cs[o * 65 + sg * 4 + 1];
        res.z = xv.z + g * Cs[o * 65 + sg * 4 + 2];
        res.w = xv.w + g * Cs[o * 65 + sg * 4 + 3];
        *(float4*)(outg + oidx) = res;
    }
}

/* ---------------- launch ---------------- */
extern "C" void kernel_launch(void* const* d_in, const int* in_sizes, int n_in,
                              void* d_out, int out_size)
{
    const float* x            = (const float*)d_in[0];
    const float* s            = (const float*)d_in[1];
    const float* ln_w         = (const float*)d_in[2];
    const float* ln_b         = (const float*)d_in[3];
    const float* gamma        = (const float*)d_in[4];
    const float* dw_fc_w      = (const float*)d_in[5];
    const float* dw_fc_b      = (const float*)d_in[6];
    const float* dw_bank      = (const float*)d_in[7];
    const float* dw_bias_bank = (const float*)d_in[8];
    const float* pw1_fc_w     = (const float*)d_in[9];
    const float* pw1_fc_b     = (const float*)d_in[10];
    const float* pw1_bank     = (const float*)d_in[11];
    const float* pw1_bias_bank= (const float*)d_in[12];
    const float* pw2_fc_w     = (const float*)d_in[13];
    const float* pw2_fc_b     = (const float*)d_in[14];
    const float* pw2_bank     = (const float*)d_in[15];
    const float* pw2_bias_bank= (const float*)d_in[16];
    float* outp = (float*)d_out;

    k_weights<<<dim3(146, 3, NB), 256>>>(s,
        dw_fc_w, dw_fc_b, dw_bank, dw_bias_bank,
        pw1_fc_w, pw1_fc_b, pw1_bank, pw1_bias_bank,
        pw2_fc_w, pw2_fc_b, pw2_bank, pw2_bias_bank);

    k_dwconv<<<dim3(72, CH, NB), 192>>>(x);

    k_ln<<<dim3(VOX / 64, NB, 1), 256>>>(ln_w, ln_b);

    k_gemm1<<<dim3(6, VOX / 128, NB), 256>>>();

    k_gemm2<<<dim3(VOX / 64, NB, 1), 256>>>(x, gamma, outp);
}

// round 2
// speedup vs baseline: 1.9107x; 1.9107x over previous
#include <cuda_runtime.h>
#include <cuda_bf16.h>

#define SPD   48
#define VOX   (48*48*48)      /* 110592 */
#define CH    96
#define CH4   384
#define LATD  8
#define STY   128
#define NB    2

/* ---------------- scratch (device globals; no allocation) ---------------- */
__device__ float g_wdw[NB * CH * 343];
__device__ float g_bdw[NB * CH];
__device__ __nv_bfloat16 g_W1h[NB * CH4 * CH];               /* pw1 weights bf16 [o][c] */
__device__ float g_b1[NB * CH4];
__device__ __nv_bfloat16 g_W2h[NB * CH * CH4];               /* pw2 weights bf16 [o][c4] */
__device__ float g_b2[NB * CH];
__device__ float g_h[(size_t)NB * CH * VOX];                 /* dwconv out, [b][c][v] fp32 */
__device__ __nv_bfloat16 g_hn[(size_t)NB * VOX * CH];        /* LN out, [b][v][c] bf16     */
__device__ __nv_bfloat16 g_y1[(size_t)NB * VOX * CH4];       /* gelu(pw1) [b][v][4c] bf16  */

/* ---------------- helpers ---------------- */
__device__ __forceinline__ unsigned long long pack2(float lo, float hi) {
    unsigned long long r;
    asm("mov.b64 %0, {%1, %2};" : "=l"(r) : "f"(lo), "f"(hi));
    return r;
}
__device__ __forceinline__ void unpack2(unsigned long long v, float& lo, float& hi) {
    asm("mov.b64 {%0, %1}, %2;" : "=f"(lo), "=f"(hi) : "l"(v));
}
__device__ __forceinline__ void fma2(unsigned long long& d, unsigned long long a, unsigned long long b) {
    asm("fma.rn.f32x2 %0, %1, %2, %0;" : "+l"(d) : "l"(a), "l"(b));
}
__device__ __forceinline__ float gelu_fast(float x) {
    float u = 0.7978845608f * x * (1.0f + 0.044715f * x * x);
    float t;
    asm("tanh.approx.f32 %0, %1;" : "=f"(t) : "f"(u));
    return 0.5f * x * (1.0f + t);
}
__device__ __forceinline__ void ldsm_x4(unsigned& r0, unsigned& r1, unsigned& r2, unsigned& r3,
                                        unsigned addr) {
    asm volatile("ldmatrix.sync.aligned.m8n8.x4.shared.b16 {%0,%1,%2,%3}, [%4];"
                 : "=r"(r0), "=r"(r1), "=r"(r2), "=r"(r3) : "r"(addr));
}
__device__ __forceinline__ void mma16816(float* c, const unsigned* a, const unsigned* b) {
    asm volatile("mma.sync.aligned.m16n8k16.row.col.f32.bf16.bf16.f32 "
                 "{%0,%1,%2,%3}, {%4,%5,%6,%7}, {%8,%9}, {%0,%1,%2,%3};"
                 : "+f"(c[0]), "+f"(c[1]), "+f"(c[2]), "+f"(c[3])
                 : "r"(a[0]), "r"(a[1]), "r"(a[2]), "r"(a[3]), "r"(b[0]), "r"(b[1]));
}

/* ---------------- K0: hyper-weight materialization ---------------- */
__global__ void k_weights(const float* __restrict__ s,
    const float* __restrict__ dw_fc_w,  const float* __restrict__ dw_fc_b,
    const float* __restrict__ dw_bank,  const float* __restrict__ dw_bias_bank,
    const float* __restrict__ pw1_fc_w, const float* __restrict__ pw1_fc_b,
    const float* __restrict__ pw1_bank, const float* __restrict__ pw1_bias_bank,
    const float* __restrict__ pw2_fc_w, const float* __restrict__ pw2_fc_b,
    const float* __restrict__ pw2_bank, const float* __restrict__ pw2_bias_bank)
{
    const int stage = blockIdx.y;
    const int b = blockIdx.z;
    __shared__ float z[LATD];
    const float* fcw = (stage == 0) ? dw_fc_w : (stage == 1) ? pw1_fc_w : pw2_fc_w;
    const float* fcb = (stage == 0) ? dw_fc_b : (stage == 1) ? pw1_fc_b : pw2_fc_b;
    if (threadIdx.x < LATD) {
        float acc = fcb[threadIdx.x];
        for (int j = 0; j < STY; j++) acc += s[b * STY + j] * fcw[threadIdx.x * STY + j];
        z[threadIdx.x] = acc;
    }
    __syncthreads();
    const int idx = blockIdx.x * blockDim.x + threadIdx.x;
    if (stage == 0) {
        const int NW = CH * 343;
        if (idx < NW) {
            float a = 0.f;
            #pragma unroll
            for (int l = 0; l < LATD; l++) a += dw_bank[(size_t)idx * LATD + l] * z[l];
            g_wdw[b * NW + idx] = a;
        } else if (idx < NW + CH) {
            const int c = idx - NW; float a = 0.f;
            #pragma unroll
            for (int l = 0; l < LATD; l++) a += dw_bias_bank[c * LATD + l] * z[l];
            g_bdw[b * CH + c] = a;
        }
    } else if (stage == 1) {
        const int NW = CH4 * CH;
        if (idx < NW) {
            float a = 0.f;
            #pragma unroll
            for (int l = 0; l < LATD; l++) a += pw1_bank[(size_t)idx * LATD + l] * z[l];
            g_W1h[b * NW + idx] = __float2bfloat16(a);
        } else if (idx < NW + CH4) {
            const int o = idx - NW; float a = 0.f;
            #pragma unroll
            for (int l = 0; l < LATD; l++) a += pw1_bias_bank[o * LATD + l] * z[l];
            g_b1[b * CH4 + o] = a;
        }
    } else {
        const int NW = CH * CH4;
        if (idx < NW) {
            float a = 0.f;
            #pragma unroll
            for (int l = 0; l < LATD; l++) a += pw2_bank[(size_t)idx * LATD + l] * z[l];
            g_W2h[b * NW + idx] = __float2bfloat16(a);
        } else if (idx < NW + CH) {
            const int o = idx - NW; float a = 0.f;
            #pragma unroll
            for (int l = 0; l < LATD; l++) a += pw2_bias_bank[o * LATD + l] * z[l];
            g_b2[b * CH + o] = a;
        }
    }
}

/* ---------------- K1: depthwise 7^3 conv (pad 3), f32x2 packed ----------------
   Block: one (b,c), tile 4(d) x 8(h) x 48(w). 192 threads, each 8 outputs along w. */
__global__ __launch_bounds__(192) void k_dwconv(const float* __restrict__ x)
{
    const int tile = blockIdx.x;            /* 0..71: 12 d-tiles x 6 h-tiles */
    const int c = blockIdx.y, b = blockIdx.z;
    const int d_t = tile / 6, h_t = tile % 6;

    __shared__ __align__(16) float smx[10 * 14 * 56];
    __shared__ __align__(8) float2 wgt2[343];
    __shared__ float sbias;

    const float* xin = x + (size_t)(b * CH + c) * VOX;
    for (int i = threadIdx.x; i < 343; i += 192) {
        const float wv = g_wdw[(b * CH + c) * 343 + i];
        wgt2[i] = make_float2(wv, wv);
    }
    if (threadIdx.x == 0) sbias = g_bdw[b * CH + c];

    const int d0 = d_t * 4 - 3, h0 = h_t * 8 - 3;
    for (int i = threadIdx.x; i < 10 * 14 * 56; i += 192) {
        const int dd = i / (14 * 56);
        const int r  = i - dd * (14 * 56);
        const int hh = r / 56;
        const int ww = r - hh * 56;
        const int gd = d0 + dd, gh = h0 + hh, gw = ww - 3;
        float v = 0.f;
        if ((unsigned)gd < 48u && (unsigned)gh < 48u && (unsigned)gw < 48u)
            v = xin[gd * 2304 + gh * 48 + gw];
        smx[i] = v;
    }
    __syncthreads();

    const int wseg = threadIdx.x % 6;
    const int dh   = threadIdx.x / 6;       /* 0..31 */
    const int ld = dh >> 3, lh = dh & 7;
    const int w0 = wseg * 8;

    unsigned long long acc2[4] = {0ull, 0ull, 0ull, 0ull};

    #pragma unroll 1
    for (int kd = 0; kd < 7; kd++) {
        #pragma unroll
        for (int kh = 0; kh < 7; kh++) {
            const float* row = &smx[(ld + kd) * 784 + (lh + kh) * 56 + w0];
            float r[16];
            *(float4*)&r[0]  = *(const float4*)&row[0];
            *(float4*)&r[4]  = *(const float4*)&row[4];
            *(float4*)&r[8]  = *(const float4*)&row[8];
            *(float4*)&r[12] = *(const float4*)&row[12];
            unsigned long long Pe[7], Po[6];
            #pragma unroll
            for (int j = 0; j < 7; j++) Pe[j] = pack2(r[2 * j], r[2 * j + 1]);
            #pragma unroll
            for (int j = 0; j < 6; j++) Po[j] = pack2(r[2 * j + 1], r[2 * j + 2]);
            const unsigned long long* wp =
                (const unsigned long long*)&wgt2[kd * 49 + kh * 7];
            #pragma unroll
            for (int kw = 0; kw < 7; kw++) {
                const unsigned long long b2 = wp[kw];
                if (kw & 1) {
                    const int base = (kw - 1) >> 1;
                    #pragma unroll
                    for (int j = 0; j < 4; j++) fma2(acc2[j], Po[base + j - (base + j > 5 ? 0 : 0)], b2);
                } else {
                    const int base = kw >> 1;
                    #pragma unroll
                    for (int j = 0; j < 4; j++) fma2(acc2[j], Pe[base + j], b2);
                }
            }
        }
    }

    const int gd = d_t * 4 + ld, gh = h_t * 8 + lh;
    float* outp = g_h + (size_t)(b * CH + c) * VOX + gd * 2304 + gh * 48 + w0;
    const float bsv = sbias;
    float a[8];
    #pragma unroll
    for (int j = 0; j < 4; j++) { unpack2(acc2[j], a[2 * j], a[2 * j + 1]); }
    #pragma unroll
    for (int i = 0; i < 8; i++) a[i] += bsv;
    *(float4*)&outp[0] = make_float4(a[0], a[1], a[2], a[3]);
    *(float4*)&outp[4] = make_float4(a[4], a[5], a[6], a[7]);
}

/* ---------------- K2: channel LayerNorm + transpose to [v][c] bf16 ---------------- */
__global__ __launch_bounds__(256) void k_ln(const float* __restrict__ ln_w,
                                            const float* __restrict__ ln_b)
{
    const int b = blockIdx.y;
    const int v0 = blockIdx.x * 64;
    __shared__ float sm[96 * 65];
    __shared__ float ps[256], ps2[256];
    __shared__ float smean[64], srstd[64];

    const float* hin = g_h + (size_t)b * CH * VOX;
    for (int i = threadIdx.x; i < 96 * 64; i += 256) {
        const int cc = i >> 6, vv = i & 63;
        sm[cc * 65 + vv] = hin[(size_t)cc * VOX + v0 + vv];
    }
    __syncthreads();
    {
        const int vv = threadIdx.x & 63, q = threadIdx.x >> 6;
        float s1 = 0.f, s2 = 0.f;
        for (int cc = q * 24; cc < q * 24 + 24; cc++) {
            const float t = sm[cc * 65 + vv]; s1 += t; s2 += t * t;
        }
        ps[threadIdx.x] = s1; ps2[threadIdx.x] = s2;
    }
    __syncthreads();
    if (threadIdx.x < 64) {
        const float s1 = ps[threadIdx.x] + ps[threadIdx.x + 64] + ps[threadIdx.x + 128] + ps[threadIdx.x + 192];
        const float s2 = ps2[threadIdx.x] + ps2[threadIdx.x + 64] + ps2[threadIdx.x + 128] + ps2[threadIdx.x + 192];
        const float mean = s1 * (1.f / 96.f);
        const float var  = s2 * (1.f / 96.f) - mean * mean;
        smean[threadIdx.x] = mean;
        srstd[threadIdx.x] = rsqrtf(var + 1e-6f);
    }
    __syncthreads();
    __nv_bfloat16* outp = g_hn + (size_t)b * VOX * CH;
    for (int i = threadIdx.x; i < 64 * 48; i += 256) {
        const int vv = i / 48;
        const int cp = i - vv * 48;
        const int c0 = cp * 2;
        const float mean = smean[vv], rs = srstd[vv];
        const float a0 = (sm[c0 * 65 + vv]       - mean) * rs * ln_w[c0]     + ln_b[c0];
        const float a1 = (sm[(c0 + 1) * 65 + vv] - mean) * rs * ln_w[c0 + 1] + ln_b[c0 + 1];
        *(__nv_bfloat162*)(outp + (size_t)(v0 + vv) * CH + c0) = __floats2bfloat162_rn(a0, a1);
    }
}

/* ---------------- K3: pw1 via mma.sync bf16 (M=128v x N=64o, K=96) + GELU ----------------
   8 warps as 4(M)x2(N); warp tile 32x32. */
__global__ __launch_bounds__(256) void k_gemm1()
{
    const int nb = blockIdx.x * 64;
    const int vb = blockIdx.y * 128;
    const int b  = blockIdx.z;

    __shared__ __align__(16) union USm {
        struct { __nv_bfloat16 A[128 * 104]; __nv_bfloat16 B[64 * 104]; } ab;
        __nv_bfloat16 C[128 * 72];
    } sm;
    __shared__ float sbias[64];

    const __nv_bfloat16* Ag = g_hn + (size_t)b * VOX * CH;
    const __nv_bfloat16* Bg = g_W1h + b * CH4 * CH;
    const int tid = threadIdx.x;

    #pragma unroll
    for (int t = 0; t < 6; t++) {
        const int idx = tid + t * 256;
        const int row = idx / 12, q = idx % 12;
        *(uint4*)&sm.ab.A[row * 104 + q * 8] =
            *(const uint4*)(Ag + (size_t)(vb + row) * CH + q * 8);
    }
    #pragma unroll
    for (int t = 0; t < 3; t++) {
        const int idx = tid + t * 256;
        const int row = idx / 12, q = idx % 12;
        *(uint4*)&sm.ab.B[row * 104 + q * 8] =
            *(const uint4*)(Bg + (nb + row) * CH + q * 8);
    }
    if (tid < 64) sbias[tid] = g_b1[b * CH4 + nb + tid];
    __syncthreads();

    const int w = tid >> 5, l = tid & 31;
    const int m0 = (w >> 1) * 32, n0 = (w & 1) * 32;
    const unsigned aBase = (unsigned)__cvta_generic_to_shared(sm.ab.A);
    const unsigned bBase = (unsigned)__cvta_generic_to_shared(sm.ab.B);

    float acc[2][4][4];
    #pragma unroll
    for (int i = 0; i < 2; i++)
        #pragma unroll
        for (int j = 0; j < 4; j++)
            #pragma unroll
            for (int q = 0; q < 4; q++) acc[i][j][q] = 0.f;

    const int arow = l & 15, ahalf = l >> 4;
    const int brow = l & 7, bhalf = (l >> 3) & 1, bsub = l >> 4;

    #pragma unroll
    for (int kk = 0; kk < 6; kk++) {
        unsigned a[2][4];
        #pragma unroll
        for (int i = 0; i < 2; i++) {
            const unsigned addr = aBase +
                ((m0 + 16 * i + arow) * 104 + kk * 16 + ahalf * 8) * 2;
            ldsm_x4(a[i][0], a[i][1], a[i][2], a[i][3], addr);
        }
        unsigned bf[4][2];
        #pragma unroll
        for (int jb = 0; jb < 2; jb++) {
            const unsigned addr = bBase +
                ((n0 + 8 * (2 * jb + bsub) + brow) * 104 + kk * 16 + bhalf * 8) * 2;
            unsigned t0, t1, t2, t3;
            ldsm_x4(t0, t1, t2, t3, addr);
            bf[2 * jb][0] = t0; bf[2 * jb][1] = t1;
            bf[2 * jb + 1][0] = t2; bf[2 * jb + 1][1] = t3;
        }
        #pragma unroll
        for (int i = 0; i < 2; i++)
            #pragma unroll
            for (int j = 0; j < 4; j++)
                mma16816(acc[i][j], a[i], bf[j]);
    }
    __syncthreads();

    const int g = l >> 2, tig = l & 3;
    #pragma unroll
    for (int i = 0; i < 2; i++) {
        #pragma unroll
        for (int j = 0; j < 4; j++) {
            const int colc = n0 + 8 * j + tig * 2;
            const float bs0 = sbias[colc], bs1 = sbias[colc + 1];
            const float v0 = gelu_fast(acc[i][j][0] + bs0);
            const float v1 = gelu_fast(acc[i][j][1] + bs1);
            const float v2 = gelu_fast(acc[i][j][2] + bs0);
            const float v3 = gelu_fast(acc[i][j][3] + bs1);
            const int r0 = m0 + 16 * i + g;
            *(__nv_bfloat162*)&sm.C[r0 * 72 + colc]       = __floats2bfloat162_rn(v0, v1);
            *(__nv_bfloat162*)&sm.C[(r0 + 8) * 72 + colc] = __floats2bfloat162_rn(v2, v3);
        }
    }
    __syncthreads();
    __nv_bfloat16* Y = g_y1 + (size_t)b * VOX * CH4;
    #pragma unroll
    for (int t = 0; t < 4; t++) {
        const int idx = tid + t * 256;
        const int row = idx >> 3, q = idx & 7;
        *(uint4*)(Y + (size_t)(vb + row) * CH4 + nb + q * 8) =
            *(const uint4*)&sm.C[row * 72 + q * 8];
    }
}

/* ---------------- K4: pw2 via mma.sync bf16 (M=128v x N=96o, K=384) + residual ----------------
   8 warps as 4(M)x2(N); warp tile 32x48. K chunks of 96. */
__global__ __launch_bounds__(256) void k_gemm2(const float* __restrict__ x,
                                               const float* __restrict__ gamma,
                                               float* __restrict__ outg)
{
    const int vb = blockIdx.x * 128;
    const int b  = blockIdx.y;

    __shared__ __align__(16) union USm2 {
        struct { __nv_bfloat16 A[128 * 104]; __nv_bfloat16 B[96 * 104]; } ab;
        float C[96 * 128];
    } sm;
    __shared__ float sbias[96], sgam[96];

    const __nv_bfloat16* Ag = g_y1 + (size_t)b * VOX * CH4;
    const __nv_bfloat16* Bg = g_W2h + b * CH * CH4;
    const int tid = threadIdx.x;
    if (tid < 96) { sbias[tid] = g_b2[b * CH + tid]; sgam[tid] = gamma[tid]; }

    const int w = tid >> 5, l = tid & 31;
    const int m0 = (w >> 1) * 32, n0 = (w & 1) * 48;
    const unsigned aBase = (unsigned)__cvta_generic_to_shared(sm.ab.A);
    const unsigned bBase = (unsigned)__cvta_generic_to_shared(sm.ab.B);

    float acc[2][6][4];
    #pragma unroll
    for (int i = 0; i < 2; i++)
        #pragma unroll
        for (int j = 0; j < 6; j++)
            #pragma unroll
            for (int q = 0; q < 4; q++) acc[i][j][q] = 0.f;

    const int arow = l & 15, ahalf = l >> 4;
    const int brow = l & 7, bhalf = (l >> 3) & 1, bsub = l >> 4;

    for (int kc = 0; kc < 4; kc++) {
        const int k0 = kc * 96;
        #pragma unroll
        for (int t = 0; t < 6; t++) {
            const int idx = tid + t * 256;
            const int row = idx / 12, q = idx % 12;
            *(uint4*)&sm.ab.A[row * 104 + q * 8] =
                *(const uint4*)(Ag + (size_t)(vb + row) * CH4 + k0 + q * 8);
        }
        #pragma unroll
        for (int t = 0; t < 5; t++) {
            const int idx = tid + t * 256;
            if (idx < 1152) {
                const int row = idx / 12, q = idx % 12;
                *(uint4*)&sm.ab.B[row * 104 + q * 8] =
                    *(const uint4*)(Bg + row * CH4 + k0 + q * 8);
            }
        }
        __syncthreads();

        #pragma unroll
        for (int kk = 0; kk < 6; kk++) {
            unsigned a[2][4];
            #pragma unroll
            for (int i = 0; i < 2; i++) {
                const unsigned addr = aBase +
                    ((m0 + 16 * i + arow) * 104 + kk * 16 + ahalf * 8) * 2;
                ldsm_x4(a[i][0], a[i][1], a[i][2], a[i][3], addr);
            }
            unsigned bf[6][2];
            #pragma unroll
            for (int jb = 0; jb < 3; jb++) {
                const unsigned addr = bBase +
                    ((n0 + 8 * (2 * jb + bsub) + brow) * 104 + kk * 16 + bhalf * 8) * 2;
                unsigned t0, t1, t2, t3;
                ldsm_x4(t0, t1, t2, t3, addr);
                bf[2 * jb][0] = t0; bf[2 * jb][1] = t1;
                bf[2 * jb + 1][0] = t2; bf[2 * jb + 1][1] = t3;
            }
            #pragma unroll
            for (int i = 0; i < 2; i++)
                #pragma unroll
                for (int j = 0; j < 6; j++)
                    mma16816(acc[i][j], a[i], bf[j]);
        }
        __syncthreads();
    }

    /* transpose through smem: C[o][m] fp32 */
    const int g = l >> 2, tig = l & 3;
    #pragma unroll
    for (int i = 0; i < 2; i++) {
        #pragma unroll
        for (int j = 0; j < 6; j++) {
            const int col = n0 + 8 * j + tig * 2;
            const int r0 = m0 + 16 * i + g;
            sm.C[col * 128 + r0]           = acc[i][j][0] + sbias[col];
            sm.C[(col + 1) * 128 + r0]     = acc[i][j][1] + sbias[col + 1];
            sm.C[col * 128 + r0 + 8]       = acc[i][j][2] + sbias[col];
            sm.C[(col + 1) * 128 + r0 + 8] = acc[i][j][3] + sbias[col + 1];
        }
    }
    __syncthreads();

    #pragma unroll
    for (int t = 0; t < 12; t++) {
        const int idx = tid + t * 256;
        const int row = idx >> 5, q = idx & 31;
        const size_t oidx = (size_t)(b * CH + row) * VOX + vb + q * 4;
        const float gm = sgam[row];
        const float4 xv = *(const float4*)(x + oidx);
        const float4 cv = *(const float4*)&sm.C[row * 128 + q * 4];
        float4 res;
        res.x = xv.x + gm * cv.x;
        res.y = xv.y + gm * cv.y;
        res.z = xv.z + gm * cv.z;
        res.w = xv.w + gm * cv.w;
        *(float4*)(outg + oidx) = res;
    }
}

/* ---------------- launch ---------------- */
extern "C" void kernel_launch(void* const* d_in, const int* in_sizes, int n_in,
                              void* d_out, int out_size)
{
    const float* x            = (const float*)d_in[0];
    const float* s            = (const float*)d_in[1];
    const float* ln_w         = (const float*)d_in[2];
    const float* ln_b         = (const float*)d_in[3];
    const float* gamma        = (const float*)d_in[4];
    const float* dw_fc_w      = (const float*)d_in[5];
    const float* dw_fc_b      = (const float*)d_in[6];
    const float* dw_bank      = (const float*)d_in[7];
    const float* dw_bias_bank = (const float*)d_in[8];
    const float* pw1_fc_w     = (const float*)d_in[9];
    const float* pw1_fc_b     = (const float*)d_in[10];
    const float* pw1_bank     = (const float*)d_in[11];
    const float* pw1_bias_bank= (const float*)d_in[12];
    const float* pw2_fc_w     = (const float*)d_in[13];
    const float* pw2_fc_b     = (const float*)d_in[14];
    const float* pw2_bank     = (const float*)d_in[15];
    const float* pw2_bias_bank= (const float*)d_in[16];
    float* outp = (float*)d_out;

    k_weights<<<dim3(146, 3, NB), 256>>>(s,
        dw_fc_w, dw_fc_b, dw_bank, dw_bias_bank,
        pw1_fc_w, pw1_fc_b, pw1_bank, pw1_bias_bank,
        pw2_fc_w, pw2_fc_b, pw2_bank, pw2_bias_bank);

    k_dwconv<<<dim3(72, CH, NB), 192>>>(x);

    k_ln<<<dim3(VOX / 64, NB, 1), 256>>>(ln_w, ln_b);

    k_gemm1<<<dim3(6, VOX / 128, NB), 256>>>();

    k_gemm2<<<dim3(VOX / 128, NB, 1), 256>>>(x, gamma, outp);
}

// round 3
// speedup vs baseline: 2.3223x; 1.2154x over previous
#include <cuda_runtime.h>
#include <cuda_bf16.h>

#define SPD   48
#define VOX   (48*48*48)      /* 110592 */
#define CH    96
#define CH4   384
#define LATD  8
#define STY   128
#define NB    2

/* ---------------- scratch (device globals; no allocation) ---------------- */
__device__ float g_wdw[NB * CH * 343];
__device__ float g_bdw[NB * CH];
__device__ __nv_bfloat16 g_W1h[NB * CH4 * CH];               /* pw1 weights bf16 [o][c] */
__device__ float g_b1[NB * CH4];
__device__ __nv_bfloat16 g_W2h[NB * CH * CH4];               /* pw2 weights bf16 [o][c4] */
__device__ float g_b2[NB * CH];
__device__ __nv_bfloat16 g_hb[(size_t)NB * CH * VOX];        /* dwconv out, [b][c][v] bf16 */
__device__ __nv_bfloat16 g_hn[(size_t)NB * VOX * CH];        /* LN out, [b][v][c] bf16     */
__device__ __nv_bfloat16 g_y1[(size_t)NB * VOX * CH4];       /* gelu(pw1) [b][v][4c] bf16  */

/* ---------------- helpers ---------------- */
__device__ __forceinline__ unsigned long long pack2(float lo, float hi) {
    unsigned long long r;
    asm("mov.b64 %0, {%1, %2};" : "=l"(r) : "f"(lo), "f"(hi));
    return r;
}
__device__ __forceinline__ void unpack2(unsigned long long v, float& lo, float& hi) {
    asm("mov.b64 {%0, %1}, %2;" : "=f"(lo), "=f"(hi) : "l"(v));
}
__device__ __forceinline__ void fma2(unsigned long long& d, unsigned long long a, unsigned long long b) {
    asm("fma.rn.f32x2 %0, %1, %2, %0;" : "+l"(d) : "l"(a), "l"(b));
}
__device__ __forceinline__ float gelu_fast(float x) {
    float u = 0.7978845608f * x * (1.0f + 0.044715f * x * x);
    float t;
    asm("tanh.approx.f32 %0, %1;" : "=f"(t) : "f"(u));
    return 0.5f * x * (1.0f + t);
}
__device__ __forceinline__ void ldsm_x4(unsigned& r0, unsigned& r1, unsigned& r2, unsigned& r3,
                                        unsigned addr) {
    asm volatile("ldmatrix.sync.aligned.m8n8.x4.shared.b16 {%0,%1,%2,%3}, [%4];"
                 : "=r"(r0), "=r"(r1), "=r"(r2), "=r"(r3) : "r"(addr));
}
__device__ __forceinline__ void mma16816(float* c, const unsigned* a, const unsigned* b) {
    asm volatile("mma.sync.aligned.m16n8k16.row.col.f32.bf16.bf16.f32 "
                 "{%0,%1,%2,%3}, {%4,%5,%6,%7}, {%8,%9}, {%0,%1,%2,%3};"
                 : "+f"(c[0]), "+f"(c[1]), "+f"(c[2]), "+f"(c[3])
                 : "r"(a[0]), "r"(a[1]), "r"(a[2]), "r"(a[3]), "r"(b[0]), "r"(b[1]));
}

/* ---------------- K0: hyper-weight materialization ---------------- */
__global__ void k_weights(const float* __restrict__ s,
    const float* __restrict__ dw_fc_w,  const float* __restrict__ dw_fc_b,
    const float* __restrict__ dw_bank,  const float* __restrict__ dw_bias_bank,
    const float* __restrict__ pw1_fc_w, const float* __restrict__ pw1_fc_b,
    const float* __restrict__ pw1_bank, const float* __restrict__ pw1_bias_bank,
    const float* __restrict__ pw2_fc_w, const float* __restrict__ pw2_fc_b,
    const float* __restrict__ pw2_bank, const float* __restrict__ pw2_bias_bank)
{
    const int stage = blockIdx.y;
    const int b = blockIdx.z;
    __shared__ float z[LATD];
    const float* fcw = (stage == 0) ? dw_fc_w : (stage == 1) ? pw1_fc_w : pw2_fc_w;
    const float* fcb = (stage == 0) ? dw_fc_b : (stage == 1) ? pw1_fc_b : pw2_fc_b;
    if (threadIdx.x < LATD) {
        float acc = fcb[threadIdx.x];
        for (int j = 0; j < STY; j++) acc += s[b * STY + j] * fcw[threadIdx.x * STY + j];
        z[threadIdx.x] = acc;
    }
    __syncthreads();
    const int idx = blockIdx.x * blockDim.x + threadIdx.x;
    if (stage == 0) {
        const int NW = CH * 343;
        if (idx < NW) {
            float a = 0.f;
            #pragma unroll
            for (int l = 0; l < LATD; l++) a += dw_bank[(size_t)idx * LATD + l] * z[l];
            g_wdw[b * NW + idx] = a;
        } else if (idx < NW + CH) {
            const int c = idx - NW; float a = 0.f;
            #pragma unroll
            for (int l = 0; l < LATD; l++) a += dw_bias_bank[c * LATD + l] * z[l];
            g_bdw[b * CH + c] = a;
        }
    } else if (stage == 1) {
        const int NW = CH4 * CH;
        if (idx < NW) {
            float a = 0.f;
            #pragma unroll
            for (int l = 0; l < LATD; l++) a += pw1_bank[(size_t)idx * LATD + l] * z[l];
            g_W1h[b * NW + idx] = __float2bfloat16(a);
        } else if (idx < NW + CH4) {
            const int o = idx - NW; float a = 0.f;
            #pragma unroll
            for (int l = 0; l < LATD; l++) a += pw1_bias_bank[o * LATD + l] * z[l];
            g_b1[b * CH4 + o] = a;
        }
    } else {
        const int NW = CH * CH4;
        if (idx < NW) {
            float a = 0.f;
            #pragma unroll
            for (int l = 0; l < LATD; l++) a += pw2_bank[(size_t)idx * LATD + l] * z[l];
            g_W2h[b * NW + idx] = __float2bfloat16(a);
        } else if (idx < NW + CH) {
            const int o = idx - NW; float a = 0.f;
            #pragma unroll
            for (int l = 0; l < LATD; l++) a += pw2_bias_bank[o * LATD + l] * z[l];
            g_b2[b * CH + o] = a;
        }
    }
}

/* ---------------- K1: depthwise 7^3 conv, row-sliding f32x2 ----------------
   Block: one (b,c), tile 8(d) x 8(h) x 48(w). 96 threads, each 8w x 4h outputs.
   Each input row is loaded+packed ONCE per kd and applied to all overlapping
   (kh, oh) pairs. Output written bf16. */
__global__ __launch_bounds__(96) void k_dwconv(const float* __restrict__ x)
{
    const int d_t = blockIdx.x / 6, h_t = blockIdx.x % 6;
    const int c = blockIdx.y, b = blockIdx.z;

    __shared__ __align__(16) float smx[14 * 14 * 56];   /* 43904 B */
    __shared__ __align__(8) float2 wgt2[343];           /*  2744 B */
    __shared__ float sbias;

    const float* xin = x + (size_t)(b * CH + c) * VOX;
    for (int i = threadIdx.x; i < 343; i += 96) {
        const float wv = g_wdw[(b * CH + c) * 343 + i];
        wgt2[i] = make_float2(wv, wv);
    }
    if (threadIdx.x == 0) sbias = g_bdw[b * CH + c];

    const int d0 = d_t * 8 - 3, h0 = h_t * 8 - 3;
    for (int i = threadIdx.x; i < 14 * 14 * 56; i += 96) {
        const int dd = i / 784;
        const int r  = i - dd * 784;
        const int hh = r / 56;
        const int ww = r - hh * 56;
        const int gd = d0 + dd, gh = h0 + hh, gw = ww - 3;
        float v = 0.f;
        if ((unsigned)gd < 48u && (unsigned)gh < 48u && (unsigned)gw < 48u)
            v = xin[gd * 2304 + gh * 48 + gw];
        smx[i] = v;
    }
    __syncthreads();

    const int wseg = threadIdx.x % 6;             /* 0..5 -> w0 */
    const int hseg = (threadIdx.x / 6) & 1;       /* 0..1 -> lh */
    const int ld   = threadIdx.x / 12;            /* 0..7 */
    const int w0 = wseg * 8, lh = hseg * 4;

    unsigned long long acc2[4][4];                /* [oh][wpair] */
    #pragma unroll
    for (int i = 0; i < 4; i++)
        #pragma unroll
        for (int j = 0; j < 4; j++) acc2[i][j] = 0ull;

    #pragma unroll 1
    for (int kd = 0; kd < 7; kd++) {
        const float* plane = &smx[(ld + kd) * 784];
        #pragma unroll
        for (int hr = 0; hr < 10; hr++) {
            const float* row = plane + (lh + hr) * 56 + w0;
            float r[16];
            *(float4*)&r[0]  = *(const float4*)&row[0];
            *(float4*)&r[4]  = *(const float4*)&row[4];
            *(float4*)&r[8]  = *(const float4*)&row[8];
            *(float4*)&r[12] = *(const float4*)&row[12];
            unsigned long long Pe[7], Po[6];
            #pragma unroll
            for (int j = 0; j < 7; j++) Pe[j] = pack2(r[2 * j], r[2 * j + 1]);
            #pragma unroll
            for (int j = 0; j < 6; j++) Po[j] = pack2(r[2 * j + 1], r[2 * j + 2]);
            #pragma unroll
            for (int oh = 0; oh < 4; oh++) {
                const int kh = hr - oh;
                if (kh >= 0 && kh < 7) {
                    const unsigned long long* wp =
                        (const unsigned long long*)&wgt2[kd * 49 + kh * 7];
                    #pragma unroll
                    for (int kw = 0; kw < 7; kw++) {
                        const unsigned long long b2 = wp[kw];
                        const int t = kw >> 1;
                        if (kw & 1) {
                            #pragma unroll
                            for (int j = 0; j < 4; j++) fma2(acc2[oh][j], Po[t + j], b2);
                        } else {
                            #pragma unroll
                            for (int j = 0; j < 4; j++) fma2(acc2[oh][j], Pe[t + j], b2);
                        }
                    }
                }
            }
        }
    }

    const float bsv = sbias;
    const int gd = d_t * 8 + ld;
    __nv_bfloat16* obase = g_hb + (size_t)(b * CH + c) * VOX + gd * 2304;
    #pragma unroll
    for (int oh = 0; oh < 4; oh++) {
        const int gh = h_t * 8 + lh + oh;
        float a[8];
        #pragma unroll
        for (int j = 0; j < 4; j++) { unpack2(acc2[oh][j], a[2 * j], a[2 * j + 1]); }
        unsigned uw[4];
        #pragma unroll
        for (int j = 0; j < 4; j++) {
            const __nv_bfloat162 p = __floats2bfloat162_rn(a[2 * j] + bsv, a[2 * j + 1] + bsv);
            uw[j] = *(const unsigned*)&p;
        }
        *(uint4*)(obase + gh * 48 + w0) = make_uint4(uw[0], uw[1], uw[2], uw[3]);
    }
}

/* ---------------- K2: channel LayerNorm + transpose to [v][c] bf16 ---------------- */
__global__ __launch_bounds__(256) void k_ln(const float* __restrict__ ln_w,
                                            const float* __restrict__ ln_b)
{
    const int b = blockIdx.y;
    const int v0 = blockIdx.x * 64;
    __shared__ float sm[96 * 65];
    __shared__ float ps[256], ps2[256];
    __shared__ float smean[64], srstd[64];

    const __nv_bfloat16* hin = g_hb + (size_t)b * CH * VOX;
    for (int i = threadIdx.x; i < 96 * 32; i += 256) {
        const int cc = i >> 5, p = i & 31;
        const float2 f = __bfloat1622float2(
            *(const __nv_bfloat162*)(hin + (size_t)cc * VOX + v0 + 2 * p));
        sm[cc * 65 + 2 * p]     = f.x;
        sm[cc * 65 + 2 * p + 1] = f.y;
    }
    __syncthreads();
    {
        const int vv = threadIdx.x & 63, q = threadIdx.x >> 6;
        float s1 = 0.f, s2 = 0.f;
        for (int cc = q * 24; cc < q * 24 + 24; cc++) {
            const float t = sm[cc * 65 + vv]; s1 += t; s2 += t * t;
        }
        ps[threadIdx.x] = s1; ps2[threadIdx.x] = s2;
    }
    __syncthreads();
    if (threadIdx.x < 64) {
        const float s1 = ps[threadIdx.x] + ps[threadIdx.x + 64] + ps[threadIdx.x + 128] + ps[threadIdx.x + 192];
        const float s2 = ps2[threadIdx.x] + ps2[threadIdx.x + 64] + ps2[threadIdx.x + 128] + ps2[threadIdx.x + 192];
        const float mean = s1 * (1.f / 96.f);
        const float var  = s2 * (1.f / 96.f) - mean * mean;
        smean[threadIdx.x] = mean;
        srstd[threadIdx.x] = rsqrtf(var + 1e-6f);
    }
    __syncthreads();
    __nv_bfloat16* outp = g_hn + (size_t)b * VOX * CH;
    for (int i = threadIdx.x; i < 64 * 48; i += 256) {
        const int vv = i / 48;
        const int cp = i - vv * 48;
        const int c0 = cp * 2;
        const float mean = smean[vv], rs = srstd[vv];
        const float a0 = (sm[c0 * 65 + vv]       - mean) * rs * ln_w[c0]     + ln_b[c0];
        const float a1 = (sm[(c0 + 1) * 65 + vv] - mean) * rs * ln_w[c0 + 1] + ln_b[c0 + 1];
        *(__nv_bfloat162*)(outp + (size_t)(v0 + vv) * CH + c0) = __floats2bfloat162_rn(a0, a1);
    }
}

/* ---------------- K3: pw1 via mma.sync bf16 (M=128v x N=64o, K=96) + GELU ----------------
   8 warps as 4(M)x2(N); warp tile 32x32. */
__global__ __launch_bounds__(256) void k_gemm1()
{
    const int nb = blockIdx.x * 64;
    const int vb = blockIdx.y * 128;
    const int b  = blockIdx.z;

    __shared__ __align__(16) union USm {
        struct { __nv_bfloat16 A[128 * 104]; __nv_bfloat16 B[64 * 104]; } ab;
        __nv_bfloat16 C[128 * 72];
    } sm;
    __shared__ float sbias[64];

    const __nv_bfloat16* Ag = g_hn + (size_t)b * VOX * CH;
    const __nv_bfloat16* Bg = g_W1h + b * CH4 * CH;
    const int tid = threadIdx.x;

    #pragma unroll
    for (int t = 0; t < 6; t++) {
        const int idx = tid + t * 256;
        const int row = idx / 12, q = idx % 12;
        *(uint4*)&sm.ab.A[row * 104 + q * 8] =
            *(const uint4*)(Ag + (size_t)(vb + row) * CH + q * 8);
    }
    #pragma unroll
    for (int t = 0; t < 3; t++) {
        const int idx = tid + t * 256;
        const int row = idx / 12, q = idx % 12;
        *(uint4*)&sm.ab.B[row * 104 + q * 8] =
            *(const uint4*)(Bg + (nb + row) * CH + q * 8);
    }
    if (tid < 64) sbias[tid] = g_b1[b * CH4 + nb + tid];
    __syncthreads();

    const int w = tid >> 5, l = tid & 31;
    const int m0 = (w >> 1) * 32, n0 = (w & 1) * 32;
    const unsigned aBase = (unsigned)__cvta_generic_to_shared(sm.ab.A);
    const unsigned bBase = (unsigned)__cvta_generic_to_shared(sm.ab.B);

    float acc[2][4][4];
    #pragma unroll
    for (int i = 0; i < 2; i++)
        #pragma unroll
        for (int j = 0; j < 4; j++)
            #pragma unroll
            for (int q = 0; q < 4; q++) acc[i][j][q] = 0.f;

    const int arow = l & 15, ahalf = l >> 4;
    const int brow = l & 7, bhalf = (l >> 3) & 1, bsub = l >> 4;

    #pragma unroll
    for (int kk = 0; kk < 6; kk++) {
        unsigned a[2][4];
        #pragma unroll
        for (int i = 0; i < 2; i++) {
            const unsigned addr = aBase +
                ((m0 + 16 * i + arow) * 104 + kk * 16 + ahalf * 8) * 2;
            ldsm_x4(a[i][0], a[i][1], a[i][2], a[i][3], addr);
        }
        unsigned bf[4][2];
        #pragma unroll
        for (int jb = 0; jb < 2; jb++) {
            const unsigned addr = bBase +
                ((n0 + 8 * (2 * jb + bsub) + brow) * 104 + kk * 16 + bhalf * 8) * 2;
            unsigned t0, t1, t2, t3;
            ldsm_x4(t0, t1, t2, t3, addr);
            bf[2 * jb][0] = t0; bf[2 * jb][1] = t1;
            bf[2 * jb + 1][0] = t2; bf[2 * jb + 1][1] = t3;
        }
        #pragma unroll
        for (int i = 0; i < 2; i++)
            #pragma unroll
            for (int j = 0; j < 4; j++)
                mma16816(acc[i][j], a[i], bf[j]);
    }
    __syncthreads();

    const int g = l >> 2, tig = l & 3;
    #pragma unroll
    for (int i = 0; i < 2; i++) {
        #pragma unroll
        for (int j = 0; j < 4; j++) {
            const int colc = n0 + 8 * j + tig * 2;
            const float bs0 = sbias[colc], bs1 = sbias[colc + 1];
            const float v0 = gelu_fast(acc[i][j][0] + bs0);
            const float v1 = gelu_fast(acc[i][j][1] + bs1);
            const float v2 = gelu_fast(acc[i][j][2] + bs0);
            const float v3 = gelu_fast(acc[i][j][3] + bs1);
            const int r0 = m0 + 16 * i + g;
            *(__nv_bfloat162*)&sm.C[r0 * 72 + colc]       = __floats2bfloat162_rn(v0, v1);
            *(__nv_bfloat162*)&sm.C[(r0 + 8) * 72 + colc] = __floats2bfloat162_rn(v2, v3);
        }
    }
    __syncthreads();
    __nv_bfloat16* Y = g_y1 + (size_t)b * VOX * CH4;
    #pragma unroll
    for (int t = 0; t < 4; t++) {
        const int idx = tid + t * 256;
        const int row = idx >> 3, q = idx & 7;
        *(uint4*)(Y + (size_t)(vb + row) * CH4 + nb + q * 8) =
            *(const uint4*)&sm.C[row * 72 + q * 8];
    }
}

/* ---------------- K4: pw2 via mma.sync bf16 (M=128v x N=96o, K=384) + residual ---------------- */
__global__ __launch_bounds__(256) void k_gemm2(const float* __restrict__ x,
                                               const float* __restrict__ gamma,
                                               float* __restrict__ outg)
{
    const int vb = blockIdx.x * 128;
    const int b  = blockIdx.y;

    __shared__ __align__(16) union USm2 {
        struct { __nv_bfloat16 A[128 * 104]; __nv_bfloat16 B[96 * 104]; } ab;
        float C[96 * 128];
    } sm;
    __shared__ float sbias[96], sgam[96];

    const __nv_bfloat16* Ag = g_y1 + (size_t)b * VOX * CH4;
    const __nv_bfloat16* Bg = g_W2h + b * CH * CH4;
    const int tid = threadIdx.x;
    if (tid < 96) { sbias[tid] = g_b2[b * CH + tid]; sgam[tid] = gamma[tid]; }

    const int w = tid >> 5, l = tid & 31;
    const int m0 = (w >> 1) * 32, n0 = (w & 1) * 48;
    const unsigned aBase = (unsigned)__cvta_generic_to_shared(sm.ab.A);
    const unsigned bBase = (unsigned)__cvta_generic_to_shared(sm.ab.B);

    float acc[2][6][4];
    #pragma unroll
    for (int i = 0; i < 2; i++)
        #pragma unroll
        for (int j = 0; j < 6; j++)
            #pragma unroll
            for (int q = 0; q < 4; q++) acc[i][j][q] = 0.f;

    const int arow = l & 15, ahalf = l >> 4;
    const int brow = l & 7, bhalf = (l >> 3) & 1, bsub = l >> 4;

    for (int kc = 0; kc < 4; kc++) {
        const int k0 = kc * 96;
        #pragma unroll
        for (int t = 0; t < 6; t++) {
            const int idx = tid + t * 256;
            const int row = idx / 12, q = idx % 12;
            *(uint4*)&sm.ab.A[row * 104 + q * 8] =
                *(const uint4*)(Ag + (size_t)(vb + row) * CH4 + k0 + q * 8);
        }
        #pragma unroll
        for (int t = 0; t < 5; t++) {
            const int idx = tid + t * 256;
            if (idx < 1152) {
                const int row = idx / 12, q = idx % 12;
                *(uint4*)&sm.ab.B[row * 104 + q * 8] =
                    *(const uint4*)(Bg + row * CH4 + k0 + q * 8);
            }
        }
        __syncthreads();

        #pragma unroll
        for (int kk = 0; kk < 6; kk++) {
            unsigned a[2][4];
            #pragma unroll
            for (int i = 0; i < 2; i++) {
                const unsigned addr = aBase +
                    ((m0 + 16 * i + arow) * 104 + kk * 16 + ahalf * 8) * 2;
                ldsm_x4(a[i][0], a[i][1], a[i][2], a[i][3], addr);
            }
            unsigned bf[6][2];
            #pragma unroll
            for (int jb = 0; jb < 3; jb++) {
                const unsigned addr = bBase +
                    ((n0 + 8 * (2 * jb + bsub) + brow) * 104 + kk * 16 + bhalf * 8) * 2;
                unsigned t0, t1, t2, t3;
                ldsm_x4(t0, t1, t2, t3, addr);
                bf[2 * jb][0] = t0; bf[2 * jb][1] = t1;
                bf[2 * jb + 1][0] = t2; bf[2 * jb + 1][1] = t3;
            }
            #pragma unroll
            for (int i = 0; i < 2; i++)
                #pragma unroll
                for (int j = 0; j < 6; j++)
                    mma16816(acc[i][j], a[i], bf[j]);
        }
        __syncthreads();
    }

    const int g = l >> 2, tig = l & 3;
    #pragma unroll
    for (int i = 0; i < 2; i++) {
        #pragma unroll
        for (int j = 0; j < 6; j++) {
            const int col = n0 + 8 * j + tig * 2;
            const int r0 = m0 + 16 * i + g;
            sm.C[col * 128 + r0]           = acc[i][j][0] + sbias[col];
            sm.C[(col + 1) * 128 + r0]     = acc[i][j][1] + sbias[col + 1];
            sm.C[col * 128 + r0 + 8]       = acc[i][j][2] + sbias[col];
            sm.C[(col + 1) * 128 + r0 + 8] = acc[i][j][3] + sbias[col + 1];
        }
    }
    __syncthreads();

    #pragma unroll
    for (int t = 0; t < 12; t++) {
        const int idx = tid + t * 256;
        const int row = idx >> 5, q = idx & 31;
        const size_t oidx = (size_t)(b * CH + row) * VOX + vb + q * 4;
        const float gm = sgam[row];
        const float4 xv = *(const float4*)(x + oidx);
        const float4 cv = *(const float4*)&sm.C[row * 128 + q * 4];
        float4 res;
        res.x = xv.x + gm * cv.x;
        res.y = xv.y + gm * cv.y;
        res.z = xv.z + gm * cv.z;
        res.w = xv.w + gm * cv.w;
        *(float4*)(outg + oidx) = res;
    }
}

/* ---------------- launch ---------------- */
extern "C" void kernel_launch(void* const* d_in, const int* in_sizes, int n_in,
                              void* d_out, int out_size)
{
    const float* x            = (const float*)d_in[0];
    const float* s            = (const float*)d_in[1];
    const float* ln_w         = (const float*)d_in[2];
    const float* ln_b         = (const float*)d_in[3];
    const float* gamma        = (const float*)d_in[4];
    const float* dw_fc_w      = (const float*)d_in[5];
    const float* dw_fc_b      = (const float*)d_in[6];
    const float* dw_bank      = (const float*)d_in[7];
    const float* dw_bias_bank = (const float*)d_in[8];
    const float* pw1_fc_w     = (const float*)d_in[9];
    const float* pw1_fc_b     = (const float*)d_in[10];
    const float* pw1_bank     = (const float*)d_in[11];
    const float* pw1_bias_bank= (const float*)d_in[12];
    const float* pw2_fc_w     = (const float*)d_in[13];
    const float* pw2_fc_b     = (const float*)d_in[14];
    const float* pw2_bank     = (const float*)d_in[15];
    const float* pw2_bias_bank= (const float*)d_in[16];
    float* outp = (float*)d_out;

    k_weights<<<dim3(146, 3, NB), 256>>>(s,
        dw_fc_w, dw_fc_b, dw_bank, dw_bias_bank,
        pw1_fc_w, pw1_fc_b, pw1_bank, pw1_bias_bank,
        pw2_fc_w, pw2_fc_b, pw2_bank, pw2_bias_bank);

    k_dwconv<<<dim3(36, CH, NB), 96>>>(x);

    k_ln<<<dim3(VOX / 64, NB, 1), 256>>>(ln_w, ln_b);

    k_gemm1<<<dim3(6, VOX / 128, NB), 256>>>();

    k_gemm2<<<dim3(VOX / 128, NB, 1), 256>>>(x, gamma, outp);
}

// round 4
// speedup vs baseline: 2.6344x; 1.1344x over previous
#include <cuda_runtime.h>
#include <cuda_bf16.h>

#define SPD   48
#define VOX   (48*48*48)      /* 110592 */
#define CH    96
#define CH4   384
#define LATD  8
#define STY   128
#define NB    2

/* ---------------- scratch (device globals; no allocation) ---------------- */
__device__ float g_wdw[NB * CH * 343];
__device__ float g_bdw[NB * CH];
__device__ __nv_bfloat16 g_W1h[NB * CH4 * CH];               /* pw1 weights bf16 [o][c] */
__device__ float g_b1[NB * CH4];
__device__ __nv_bfloat16 g_W2h[NB * CH * CH4];               /* pw2 weights bf16 [o][c4] */
__device__ float g_b2[NB * CH];
__device__ __nv_bfloat16 g_hb[(size_t)NB * CH * VOX];        /* dwconv out, [b][c][v] bf16 */
__device__ __nv_bfloat16 g_hn[(size_t)NB * VOX * CH];        /* LN out, [b][v][c] bf16     */
__device__ __nv_bfloat16 g_y1[(size_t)NB * VOX * CH4];       /* gelu(pw1) [b][v][4c] bf16  */

/* ---------------- helpers ---------------- */
__device__ __forceinline__ unsigned long long pack2(float lo, float hi) {
    unsigned long long r;
    asm("mov.b64 %0, {%1, %2};" : "=l"(r) : "f"(lo), "f"(hi));
    return r;
}
__device__ __forceinline__ void unpack2(unsigned long long v, float& lo, float& hi) {
    asm("mov.b64 {%0, %1}, %2;" : "=f"(lo), "=f"(hi) : "l"(v));
}
__device__ __forceinline__ void fma2(unsigned long long& d, unsigned long long a, unsigned long long b) {
    asm("fma.rn.f32x2 %0, %1, %2, %0;" : "+l"(d) : "l"(a), "l"(b));
}
__device__ __forceinline__ float gelu_fast(float x) {
    float u = 0.7978845608f * x * (1.0f + 0.044715f * x * x);
    float t;
    asm("tanh.approx.f32 %0, %1;" : "=f"(t) : "f"(u));
    return 0.5f * x * (1.0f + t);
}
__device__ __forceinline__ void ldsm_x4(unsigned& r0, unsigned& r1, unsigned& r2, unsigned& r3,
                                        unsigned addr) {
    asm volatile("ldmatrix.sync.aligned.m8n8.x4.shared.b16 {%0,%1,%2,%3}, [%4];"
                 : "=r"(r0), "=r"(r1), "=r"(r2), "=r"(r3) : "r"(addr));
}
__device__ __forceinline__ void mma16816(float* c, const unsigned* a, const unsigned* b) {
    asm volatile("mma.sync.aligned.m16n8k16.row.col.f32.bf16.bf16.f32 "
                 "{%0,%1,%2,%3}, {%4,%5,%6,%7}, {%8,%9}, {%0,%1,%2,%3};"
                 : "+f"(c[0]), "+f"(c[1]), "+f"(c[2]), "+f"(c[3])
                 : "r"(a[0]), "r"(a[1]), "r"(a[2]), "r"(a[3]), "r"(b[0]), "r"(b[1]));
}

/* ---------------- K0: hyper-weight materialization ---------------- */
__global__ void k_weights(const float* __restrict__ s,
    const float* __restrict__ dw_fc_w,  const float* __restrict__ dw_fc_b,
    const float* __restrict__ dw_bank,  const float* __restrict__ dw_bias_bank,
    const float* __restrict__ pw1_fc_w, const float* __restrict__ pw1_fc_b,
    const float* __restrict__ pw1_bank, const float* __restrict__ pw1_bias_bank,
    const float* __restrict__ pw2_fc_w, const float* __restrict__ pw2_fc_b,
    const float* __restrict__ pw2_bank, const float* __restrict__ pw2_bias_bank)
{
    const int stage = blockIdx.y;
    const int b = blockIdx.z;
    __shared__ float z[LATD];
    const float* fcw = (stage == 0) ? dw_fc_w : (stage == 1) ? pw1_fc_w : pw2_fc_w;
    const float* fcb = (stage == 0) ? dw_fc_b : (stage == 1) ? pw1_fc_b : pw2_fc_b;
    if (threadIdx.x < LATD) {
        float acc = fcb[threadIdx.x];
        for (int j = 0; j < STY; j++) acc += s[b * STY + j] * fcw[threadIdx.x * STY + j];
        z[threadIdx.x] = acc;
    }
    __syncthreads();
    const int idx = blockIdx.x * blockDim.x + threadIdx.x;
    if (stage == 0) {
        const int NW = CH * 343;
        if (idx < NW) {
            float a = 0.f;
            #pragma unroll
            for (int l = 0; l < LATD; l++) a += dw_bank[(size_t)idx * LATD + l] * z[l];
            g_wdw[b * NW + idx] = a;
        } else if (idx < NW + CH) {
            const int c = idx - NW; float a = 0.f;
            #pragma unroll
            for (int l = 0; l < LATD; l++) a += dw_bias_bank[c * LATD + l] * z[l];
            g_bdw[b * CH + c] = a;
        }
    } else if (stage == 1) {
        const int NW = CH4 * CH;
        if (idx < NW) {
            float a = 0.f;
            #pragma unroll
            for (int l = 0; l < LATD; l++) a += pw1_bank[(size_t)idx * LATD + l] * z[l];
            g_W1h[b * NW + idx] = __float2bfloat16(a);
        } else if (idx < NW + CH4) {
            const int o = idx - NW; float a = 0.f;
            #pragma unroll
            for (int l = 0; l < LATD; l++) a += pw1_bias_bank[o * LATD + l] * z[l];
            g_b1[b * CH4 + o] = a;
        }
    } else {
        const int NW = CH * CH4;
        if (idx < NW) {
            float a = 0.f;
            #pragma unroll
            for (int l = 0; l < LATD; l++) a += pw2_bank[(size_t)idx * LATD + l] * z[l];
            g_W2h[b * NW + idx] = __float2bfloat16(a);
        } else if (idx < NW + CH) {
            const int o = idx - NW; float a = 0.f;
            #pragma unroll
            for (int l = 0; l < LATD; l++) a += pw2_bias_bank[o * LATD + l] * z[l];
            g_b2[b * CH + o] = a;
        }
    }
}

/* ---------------- K1: depthwise 7^3 conv, row-sliding f32x2 ----------------
   Block: one (b,c), tile 16(d) x 8(h) x 48(w). 384 threads (12 warps: even
   SMSP load), each 8w x 2h outputs. Dynamic smem halo 22x14x56 fp32. */
__global__ __launch_bounds__(384) void k_dwconv(const float* __restrict__ x)
{
    const int d_t = blockIdx.x / 6, h_t = blockIdx.x % 6;
    const int c = blockIdx.y, b = blockIdx.z;

    extern __shared__ __align__(16) float smx[];        /* 22*14*56 = 68992 B */
    __shared__ __align__(8) float2 wgt2[343];
    __shared__ float sbias;

    const float* xin = x + (size_t)(b * CH + c) * VOX;
    for (int i = threadIdx.x; i < 343; i += 384) {
        const float wv = g_wdw[(b * CH + c) * 343 + i];
        wgt2[i] = make_float2(wv, wv);
    }
    if (threadIdx.x == 0) sbias = g_bdw[b * CH + c];

    const int d0 = d_t * 16 - 3, h0 = h_t * 8 - 3;
    for (int i = threadIdx.x; i < 22 * 14 * 56; i += 384) {
        const int dd = i / 784;
        const int r  = i - dd * 784;
        const int hh = r / 56;
        const int ww = r - hh * 56;
        const int gd = d0 + dd, gh = h0 + hh, gw = ww - 3;
        float v = 0.f;
        if ((unsigned)gd < 48u && (unsigned)gh < 48u && (unsigned)gw < 48u)
            v = xin[gd * 2304 + gh * 48 + gw];
        smx[i] = v;
    }
    __syncthreads();

    /* thread map: wseg 0..5, hseg 0..3, ld 0..15 */
    const int wseg = threadIdx.x % 6;
    const int rr   = threadIdx.x / 6;
    const int hseg = rr & 3;
    const int ld   = rr >> 2;
    const int w0 = wseg * 8, lh = hseg * 2;

    unsigned long long acc2[2][4];                /* [oh][wpair] */
    #pragma unroll
    for (int i = 0; i < 2; i++)
        #pragma unroll
        for (int j = 0; j < 4; j++) acc2[i][j] = 0ull;

    #pragma unroll 1
    for (int kd = 0; kd < 7; kd++) {
        const float* plane = &smx[(ld + kd) * 784];
        #pragma unroll
        for (int hr = 0; hr < 8; hr++) {
            const float* row = plane + (lh + hr) * 56 + w0;
            float r[16];
            *(float4*)&r[0]  = *(const float4*)&row[0];
            *(float4*)&r[4]  = *(const float4*)&row[4];
            *(float4*)&r[8]  = *(const float4*)&row[8];
            *(float4*)&r[12] = *(const float4*)&row[12];
            unsigned long long Pe[7], Po[6];
            #pragma unroll
            for (int j = 0; j < 7; j++) Pe[j] = pack2(r[2 * j], r[2 * j + 1]);
            #pragma unroll
            for (int j = 0; j < 6; j++) Po[j] = pack2(r[2 * j + 1], r[2 * j + 2]);
            #pragma unroll
            for (int oh = 0; oh < 2; oh++) {
                const int kh = hr - oh;
                if (kh >= 0 && kh < 7) {
                    const unsigned long long* wp =
                        (const unsigned long long*)&wgt2[kd * 49 + kh * 7];
                    #pragma unroll
                    for (int kw = 0; kw < 7; kw++) {
                        const unsigned long long b2 = wp[kw];
                        const int t = kw >> 1;
                        if (kw & 1) {
                            #pragma unroll
                            for (int j = 0; j < 4; j++) fma2(acc2[oh][j], Po[t + j], b2);
                        } else {
                            #pragma unroll
                            for (int j = 0; j < 4; j++) fma2(acc2[oh][j], Pe[t + j], b2);
                        }
                    }
                }
            }
        }
    }

    const float bsv = sbias;
    const int gd = d_t * 16 + ld;
    __nv_bfloat16* obase = g_hb + (size_t)(b * CH + c) * VOX + gd * 2304;
    #pragma unroll
    for (int oh = 0; oh < 2; oh++) {
        const int gh = h_t * 8 + lh + oh;
        float a[8];
        #pragma unroll
        for (int j = 0; j < 4; j++) { unpack2(acc2[oh][j], a[2 * j], a[2 * j + 1]); }
        unsigned uw[4];
        #pragma unroll
        for (int j = 0; j < 4; j++) {
            const __nv_bfloat162 p = __floats2bfloat162_rn(a[2 * j] + bsv, a[2 * j + 1] + bsv);
            uw[j] = *(const unsigned*)&p;
        }
        *(uint4*)(obase + gh * 48 + w0) = make_uint4(uw[0], uw[1], uw[2], uw[3]);
    }
}

/* ---------------- K2: channel LayerNorm + transpose to [v][c] bf16 ---------------- */
__global__ __launch_bounds__(256) void k_ln(const float* __restrict__ ln_w,
                                            const float* __restrict__ ln_b)
{
    const int b = blockIdx.y;
    const int v0 = blockIdx.x * 64;
    __shared__ float sm[96 * 65];
    __shared__ float ps[256], ps2[256];
    __shared__ float smean[64], srstd[64];

    const __nv_bfloat16* hin = g_hb + (size_t)b * CH * VOX;
    for (int i = threadIdx.x; i < 96 * 32; i += 256) {
        const int cc = i >> 5, p = i & 31;
        const float2 f = __bfloat1622float2(
            *(const __nv_bfloat162*)(hin + (size_t)cc * VOX + v0 + 2 * p));
        sm[cc * 65 + 2 * p]     = f.x;
        sm[cc * 65 + 2 * p + 1] = f.y;
    }
    __syncthreads();
    {
        const int vv = threadIdx.x & 63, q = threadIdx.x >> 6;
        float s1 = 0.f, s2 = 0.f;
        for (int cc = q * 24; cc < q * 24 + 24; cc++) {
            const float t = sm[cc * 65 + vv]; s1 += t; s2 += t * t;
        }
        ps[threadIdx.x] = s1; ps2[threadIdx.x] = s2;
    }
    __syncthreads();
    if (threadIdx.x < 64) {
        const float s1 = ps[threadIdx.x] + ps[threadIdx.x + 64] + ps[threadIdx.x + 128] + ps[threadIdx.x + 192];
        const float s2 = ps2[threadIdx.x] + ps2[threadIdx.x + 64] + ps2[threadIdx.x + 128] + ps2[threadIdx.x + 192];
        const float mean = s1 * (1.f / 96.f);
        const float var  = s2 * (1.f / 96.f) - mean * mean;
        smean[threadIdx.x] = mean;
        srstd[threadIdx.x] = rsqrtf(var + 1e-6f);
    }
    __syncthreads();
    __nv_bfloat16* outp = g_hn + (size_t)b * VOX * CH;
    for (int i = threadIdx.x; i < 64 * 48; i += 256) {
        const int vv = i / 48;
        const int cp = i - vv * 48;
        const int c0 = cp * 2;
        const float mean = smean[vv], rs = srstd[vv];
        const float a0 = (sm[c0 * 65 + vv]       - mean) * rs * ln_w[c0]     + ln_b[c0];
        const float a1 = (sm[(c0 + 1) * 65 + vv] - mean) * rs * ln_w[c0 + 1] + ln_b[c0 + 1];
        *(__nv_bfloat162*)(outp + (size_t)(v0 + vv) * CH + c0) = __floats2bfloat162_rn(a0, a1);
    }
}

/* ---------------- K3: pw1 via mma.sync bf16 (M=128v x N=64o, K=96) + GELU ---------------- */
__global__ __launch_bounds__(256) void k_gemm1()
{
    const int nb = blockIdx.x * 64;
    const int vb = blockIdx.y * 128;
    const int b  = blockIdx.z;

    __shared__ __align__(16) union USm {
        struct { __nv_bfloat16 A[128 * 104]; __nv_bfloat16 B[64 * 104]; } ab;
        __nv_bfloat16 C[128 * 72];
    } sm;
    __shared__ float sbias[64];

    const __nv_bfloat16* Ag = g_hn + (size_t)b * VOX * CH;
    const __nv_bfloat16* Bg = g_W1h + b * CH4 * CH;
    const int tid = threadIdx.x;

    #pragma unroll
    for (int t = 0; t < 6; t++) {
        const int idx = tid + t * 256;
        const int row = idx / 12, q = idx % 12;
        *(uint4*)&sm.ab.A[row * 104 + q * 8] =
            *(const uint4*)(Ag + (size_t)(vb + row) * CH + q * 8);
    }
    #pragma unroll
    for (int t = 0; t < 3; t++) {
        const int idx = tid + t * 256;
        const int row = idx / 12, q = idx % 12;
        *(uint4*)&sm.ab.B[row * 104 + q * 8] =
            *(const uint4*)(Bg + (nb + row) * CH + q * 8);
    }
    if (tid < 64) sbias[tid] = g_b1[b * CH4 + nb + tid];
    __syncthreads();

    const int w = tid >> 5, l = tid & 31;
    const int m0 = (w >> 1) * 32, n0 = (w & 1) * 32;
    const unsigned aBase = (unsigned)__cvta_generic_to_shared(sm.ab.A);
    const unsigned bBase = (unsigned)__cvta_generic_to_shared(sm.ab.B);

    float acc[2][4][4];
    #pragma unroll
    for (int i = 0; i < 2; i++)
        #pragma unroll
        for (int j = 0; j < 4; j++)
            #pragma unroll
            for (int q = 0; q < 4; q++) acc[i][j][q] = 0.f;

    const int arow = l & 15, ahalf = l >> 4;
    const int brow = l & 7, bhalf = (l >> 3) & 1, bsub = l >> 4;

    #pragma unroll
    for (int kk = 0; kk < 6; kk++) {
        unsigned a[2][4];
        #pragma unroll
        for (int i = 0; i < 2; i++) {
            const unsigned addr = aBase +
                ((m0 + 16 * i + arow) * 104 + kk * 16 + ahalf * 8) * 2;
            ldsm_x4(a[i][0], a[i][1], a[i][2], a[i][3], addr);
        }
        unsigned bf[4][2];
        #pragma unroll
        for (int jb = 0; jb < 2; jb++) {
            const unsigned addr = bBase +
                ((n0 + 8 * (2 * jb + bsub) + brow) * 104 + kk * 16 + bhalf * 8) * 2;
            unsigned t0, t1, t2, t3;
            ldsm_x4(t0, t1, t2, t3, addr);
            bf[2 * jb][0] = t0; bf[2 * jb][1] = t1;
            bf[2 * jb + 1][0] = t2; bf[2 * jb + 1][1] = t3;
        }
        #pragma unroll
        for (int i = 0; i < 2; i++)
            #pragma unroll
            for (int j = 0; j < 4; j++)
                mma16816(acc[i][j], a[i], bf[j]);
    }
    __syncthreads();

    const int g = l >> 2, tig = l & 3;
    #pragma unroll
    for (int i = 0; i < 2; i++) {
        #pragma unroll
        for (int j = 0; j < 4; j++) {
            const int colc = n0 + 8 * j + tig * 2;
            const float bs0 = sbias[colc], bs1 = sbias[colc + 1];
            const float v0 = gelu_fast(acc[i][j][0] + bs0);
            const float v1 = gelu_fast(acc[i][j][1] + bs1);
            const float v2 = gelu_fast(acc[i][j][2] + bs0);
            const float v3 = gelu_fast(acc[i][j][3] + bs1);
            const int r0 = m0 + 16 * i + g;
            *(__nv_bfloat162*)&sm.C[r0 * 72 + colc]       = __floats2bfloat162_rn(v0, v1);
            *(__nv_bfloat162*)&sm.C[(r0 + 8) * 72 + colc] = __floats2bfloat162_rn(v2, v3);
        }
    }
    __syncthreads();
    __nv_bfloat16* Y = g_y1 + (size_t)b * VOX * CH4;
    #pragma unroll
    for (int t = 0; t < 4; t++) {
        const int idx = tid + t * 256;
        const int row = idx >> 3, q = idx & 7;
        *(uint4*)(Y + (size_t)(vb + row) * CH4 + nb + q * 8) =
            *(const uint4*)&sm.C[row * 72 + q * 8];
    }
}

/* ---------------- K4: pw2 via mma.sync bf16 (M=128v x N=96o, K=384) + residual ---------------- */
__global__ __launch_bounds__(256) void k_gemm2(const float* __restrict__ x,
                                               const float* __restrict__ gamma,
                                               float* __restrict__ outg)
{
    const int vb = blockIdx.x * 128;
    const int b  = blockIdx.y;

    __shared__ __align__(16) union USm2 {
        struct { __nv_bfloat16 A[128 * 104]; __nv_bfloat16 B[96 * 104]; } ab;
        float C[96 * 128];
    } sm;
    __shared__ float sbias[96], sgam[96];

    const __nv_bfloat16* Ag = g_y1 + (size_t)b * VOX * CH4;
    const __nv_bfloat16* Bg = g_W2h + b * CH * CH4;
    const int tid = threadIdx.x;
    if (tid < 96) { sbias[tid] = g_b2[b * CH + tid]; sgam[tid] = gamma[tid]; }

    const int w = tid >> 5, l = tid & 31;
    const int m0 = (w >> 1) * 32, n0 = (w & 1) * 48;
    const unsigned aBase = (unsigned)__cvta_generic_to_shared(sm.ab.A);
    const unsigned bBase = (unsigned)__cvta_generic_to_shared(sm.ab.B);

    float acc[2][6][4];
    #pragma unroll
    for (int i = 0; i < 2; i++)
        #pragma unroll
        for (int j = 0; j < 6; j++)
            #pragma unroll
            for (int q = 0; q < 4; q++) acc[i][j][q] = 0.f;

    const int arow = l & 15, ahalf = l >> 4;
    const int brow = l & 7, bhalf = (l >> 3) & 1, bsub = l >> 4;

    for (int kc = 0; kc < 4; kc++) {
        const int k0 = kc * 96;
        #pragma unroll
        for (int t = 0; t < 6; t++) {
            const int idx = tid + t * 256;
            const int row = idx / 12, q = idx % 12;
            *(uint4*)&sm.ab.A[row * 104 + q * 8] =
                *(const uint4*)(Ag + (size_t)(vb + row) * CH4 + k0 + q * 8);
        }
        #pragma unroll
        for (int t = 0; t < 5; t++) {
            const int idx = tid + t * 256;
            if (idx < 1152) {
                const int row = idx / 12, q = idx % 12;
                *(uint4*)&sm.ab.B[row * 104 + q * 8] =
                    *(const uint4*)(Bg + row * CH4 + k0 + q * 8);
            }
        }
        __syncthreads();

        #pragma unroll
        for (int kk = 0; kk < 6; kk++) {
            unsigned a[2][4];
            #pragma unroll
            for (int i = 0; i < 2; i++) {
                const unsigned addr = aBase +
                    ((m0 + 16 * i + arow) * 104 + kk * 16 + ahalf * 8) * 2;
                ldsm_x4(a[i][0], a[i][1], a[i][2], a[i][3], addr);
            }
            unsigned bf[6][2];
            #pragma unroll
            for (int jb = 0; jb < 3; jb++) {
                const unsigned addr = bBase +
                    ((n0 + 8 * (2 * jb + bsub) + brow) * 104 + kk * 16 + bhalf * 8) * 2;
                unsigned t0, t1, t2, t3;
                ldsm_x4(t0, t1, t2, t3, addr);
                bf[2 * jb][0] = t0; bf[2 * jb][1] = t1;
                bf[2 * jb + 1][0] = t2; bf[2 * jb + 1][1] = t3;
            }
            #pragma unroll
            for (int i = 0; i < 2; i++)
                #pragma unroll
                for (int j = 0; j < 6; j++)
                    mma16816(acc[i][j], a[i], bf[j]);
        }
        __syncthreads();
    }

    const int g = l >> 2, tig = l & 3;
    #pragma unroll
    for (int i = 0; i < 2; i++) {
        #pragma unroll
        for (int j = 0; j < 6; j++) {
            const int col = n0 + 8 * j + tig * 2;
            const int r0 = m0 + 16 * i + g;
            sm.C[col * 128 + r0]           = acc[i][j][0] + sbias[col];
            sm.C[(col + 1) * 128 + r0]     = acc[i][j][1] + sbias[col + 1];
            sm.C[col * 128 + r0 + 8]       = acc[i][j][2] + sbias[col];
            sm.C[(col + 1) * 128 + r0 + 8] = acc[i][j][3] + sbias[col + 1];
        }
    }
    __syncthreads();

    #pragma unroll
    for (int t = 0; t < 12; t++) {
        const int idx = tid + t * 256;
        const int row = idx >> 5, q = idx & 31;
        const size_t oidx = (size_t)(b * CH + row) * VOX + vb + q * 4;
        const float gm = sgam[row];
        const float4 xv = *(const float4*)(x + oidx);
        const float4 cv = *(const float4*)&sm.C[row * 128 + q * 4];
        float4 res;
        res.x = xv.x + gm * cv.x;
        res.y = xv.y + gm * cv.y;
        res.z = xv.z + gm * cv.z;
        res.w = xv.w + gm * cv.w;
        *(float4*)(outg + oidx) = res;
    }
}

/* ---------------- launch ---------------- */
extern "C" void kernel_launch(void* const* d_in, const int* in_sizes, int n_in,
                              void* d_out, int out_size)
{
    const float* x            = (const float*)d_in[0];
    const float* s            = (const float*)d_in[1];
    const float* ln_w         = (const float*)d_in[2];
    const float* ln_b         = (const float*)d_in[3];
    const float* gamma        = (const float*)d_in[4];
    const float* dw_fc_w      = (const float*)d_in[5];
    const float* dw_fc_b      = (const float*)d_in[6];
    const float* dw_bank      = (const float*)d_in[7];
    const float* dw_bias_bank = (const float*)d_in[8];
    const float* pw1_fc_w     = (const float*)d_in[9];
    const float* pw1_fc_b     = (const float*)d_in[10];
    const float* pw1_bank     = (const float*)d_in[11];
    const float* pw1_bias_bank= (const float*)d_in[12];
    const float* pw2_fc_w     = (const float*)d_in[13];
    const float* pw2_fc_b     = (const float*)d_in[14];
    const float* pw2_bank     = (const float*)d_in[15];
    const float* pw2_bias_bank= (const float*)d_in[16];
    float* outp = (float*)d_out;

    const int dwSmem = 22 * 14 * 56 * 4;   /* 68992 B dynamic */
    cudaFuncSetAttribute(k_dwconv, cudaFuncAttributeMaxDynamicSharedMemorySize, dwSmem);

    k_weights<<<dim3(146, 3, NB), 256>>>(s,
        dw_fc_w, dw_fc_b, dw_bank, dw_bias_bank,
        pw1_fc_w, pw1_fc_b, pw1_bank, pw1_bias_bank,
        pw2_fc_w, pw2_fc_b, pw2_bank, pw2_bias_bank);

    k_dwconv<<<dim3(18, CH, NB), 384, dwSmem>>>(x);

    k_ln<<<dim3(VOX / 64, NB, 1), 256>>>(ln_w, ln_b);

    k_gemm1<<<dim3(6, VOX / 128, NB), 256>>>();

    k_gemm2<<<dim3(VOX / 128, NB, 1), 256>>>(x, gamma, outp);
}

// round 5
// speedup vs baseline: 3.2783x; 1.2444x over previous
#include <cuda_runtime.h>
#include <cuda_bf16.h>

#define SPD   48
#define VOX   (48*48*48)      /* 110592 */
#define CH    96
#define CH4   384
#define LATD  8
#define STY   128
#define NB    2

/* ---------------- scratch (device globals; no allocation) ---------------- */
__device__ float g_wdw[NB * CH * 343];
__device__ float g_bdw[NB * CH];
__device__ __nv_bfloat16 g_W1h[NB * CH4 * CH];               /* pw1 weights bf16 [o][c] */
__device__ float g_b1[NB * CH4];
__device__ __nv_bfloat16 g_W2h[NB * CH * CH4];               /* pw2 weights bf16 [o][c4] */
__device__ float g_b2[NB * CH];
__device__ __nv_bfloat16 g_hb[(size_t)NB * CH * VOX];        /* dwconv out, [b][c][v] bf16 */
__device__ __nv_bfloat16 g_hn[(size_t)NB * VOX * CH];        /* LN out, [b][v][c] bf16     */

/* ---------------- helpers ---------------- */
__device__ __forceinline__ unsigned long long pack2(float lo, float hi) {
    unsigned long long r;
    asm("mov.b64 %0, {%1, %2};" : "=l"(r) : "f"(lo), "f"(hi));
    return r;
}
__device__ __forceinline__ void unpack2(unsigned long long v, float& lo, float& hi) {
    asm("mov.b64 {%0, %1}, %2;" : "=f"(lo), "=f"(hi) : "l"(v));
}
__device__ __forceinline__ void fma2(unsigned long long& d, unsigned long long a, unsigned long long b) {
    asm("fma.rn.f32x2 %0, %1, %2, %0;" : "+l"(d) : "l"(a), "l"(b));
}
__device__ __forceinline__ float gelu_fast(float x) {
    float u = 0.7978845608f * x * (1.0f + 0.044715f * x * x);
    float t;
    asm("tanh.approx.f32 %0, %1;" : "=f"(t) : "f"(u));
    return 0.5f * x * (1.0f + t);
}
__device__ __forceinline__ void ldsm_x4(unsigned& r0, unsigned& r1, unsigned& r2, unsigned& r3,
                                        unsigned addr) {
    asm volatile("ldmatrix.sync.aligned.m8n8.x4.shared.b16 {%0,%1,%2,%3}, [%4];"
                 : "=r"(r0), "=r"(r1), "=r"(r2), "=r"(r3) : "r"(addr));
}
__device__ __forceinline__ void mma16816(float* c, const unsigned* a, const unsigned* b) {
    asm volatile("mma.sync.aligned.m16n8k16.row.col.f32.bf16.bf16.f32 "
                 "{%0,%1,%2,%3}, {%4,%5,%6,%7}, {%8,%9}, {%0,%1,%2,%3};"
                 : "+f"(c[0]), "+f"(c[1]), "+f"(c[2]), "+f"(c[3])
                 : "r"(a[0]), "r"(a[1]), "r"(a[2]), "r"(a[3]), "r"(b[0]), "r"(b[1]));
}

/* ---------------- K0: hyper-weight materialization ---------------- */
__global__ void k_weights(const float* __restrict__ s,
    const float* __restrict__ dw_fc_w,  const float* __restrict__ dw_fc_b,
    const float* __restrict__ dw_bank,  const float* __restrict__ dw_bias_bank,
    const float* __restrict__ pw1_fc_w, const float* __restrict__ pw1_fc_b,
    const float* __restrict__ pw1_bank, const float* __restrict__ pw1_bias_bank,
    const float* __restrict__ pw2_fc_w, const float* __restrict__ pw2_fc_b,
    const float* __restrict__ pw2_bank, const float* __restrict__ pw2_bias_bank)
{
    const int stage = blockIdx.y;
    const int b = blockIdx.z;
    __shared__ float z[LATD];
    const float* fcw = (stage == 0) ? dw_fc_w : (stage == 1) ? pw1_fc_w : pw2_fc_w;
    const float* fcb = (stage == 0) ? dw_fc_b : (stage == 1) ? pw1_fc_b : pw2_fc_b;
    if (threadIdx.x < LATD) {
        float acc = fcb[threadIdx.x];
        for (int j = 0; j < STY; j++) acc += s[b * STY + j] * fcw[threadIdx.x * STY + j];
        z[threadIdx.x] = acc;
    }
    __syncthreads();
    const int idx = blockIdx.x * blockDim.x + threadIdx.x;
    if (stage == 0) {
        const int NW = CH * 343;
        if (idx < NW) {
            float a = 0.f;
            #pragma unroll
            for (int l = 0; l < LATD; l++) a += dw_bank[(size_t)idx * LATD + l] * z[l];
            g_wdw[b * NW + idx] = a;
        } else if (idx < NW + CH) {
            const int c = idx - NW; float a = 0.f;
            #pragma unroll
            for (int l = 0; l < LATD; l++) a += dw_bias_bank[c * LATD + l] * z[l];
            g_bdw[b * CH + c] = a;
        }
    } else if (stage == 1) {
        const int NW = CH4 * CH;
        if (idx < NW) {
            float a = 0.f;
            #pragma unroll
            for (int l = 0; l < LATD; l++) a += pw1_bank[(size_t)idx * LATD + l] * z[l];
            g_W1h[b * NW + idx] = __float2bfloat16(a);
        } else if (idx < NW + CH4) {
            const int o = idx - NW; float a = 0.f;
            #pragma unroll
            for (int l = 0; l < LATD; l++) a += pw1_bias_bank[o * LATD + l] * z[l];
            g_b1[b * CH4 + o] = a;
        }
    } else {
        const int NW = CH * CH4;
        if (idx < NW) {
            float a = 0.f;
            #pragma unroll
            for (int l = 0; l < LATD; l++) a += pw2_bank[(size_t)idx * LATD + l] * z[l];
            g_W2h[b * NW + idx] = __float2bfloat16(a);
        } else if (idx < NW + CH) {
            const int o = idx - NW; float a = 0.f;
            #pragma unroll
            for (int l = 0; l < LATD; l++) a += pw2_bias_bank[o * LATD + l] * z[l];
            g_b2[b * CH + o] = a;
        }
    }
}

/* ---------------- K1: depthwise 7^3 conv, row-sliding f32x2 ----------------
   Block: one (b,c), tile 16(d) x 16(h) x 48(w). 384 threads (12 warps), each
   8w x 4h outputs. Dynamic smem halo 22x22x56 fp32 (108 KB). */
__global__ __launch_bounds__(384) void k_dwconv(const float* __restrict__ x)
{
    const int d_t = blockIdx.x / 3, h_t = blockIdx.x % 3;
    const int c = blockIdx.y, b = blockIdx.z;

    extern __shared__ __align__(16) float smx[];        /* 22*22*56 = 108416 B */
    __shared__ __align__(8) float2 wgt2[343];
    __shared__ float sbias;

    const float* xin = x + (size_t)(b * CH + c) * VOX;
    for (int i = threadIdx.x; i < 343; i += 384) {
        const float wv = g_wdw[(b * CH + c) * 343 + i];
        wgt2[i] = make_float2(wv, wv);
    }
    if (threadIdx.x == 0) sbias = g_bdw[b * CH + c];

    const int d0 = d_t * 16 - 3, h0 = h_t * 16 - 3;
    for (int i = threadIdx.x; i < 22 * 22 * 56; i += 384) {
        const int dd = i / 1232;
        const int r  = i - dd * 1232;
        const int hh = r / 56;
        const int ww = r - hh * 56;
        const int gd = d0 + dd, gh = h0 + hh, gw = ww - 3;
        float v = 0.f;
        if ((unsigned)gd < 48u && (unsigned)gh < 48u && (unsigned)gw < 48u)
            v = xin[gd * 2304 + gh * 48 + gw];
        smx[i] = v;
    }
    __syncthreads();

    /* thread map: wseg 0..5, hseg 0..3 (4h each), ld 0..15 */
    const int wseg = threadIdx.x % 6;
    const int rr   = threadIdx.x / 6;
    const int hseg = rr & 3;
    const int ld   = rr >> 2;
    const int w0 = wseg * 8, lh = hseg * 4;

    unsigned long long acc2[4][4];                /* [oh][wpair] */
    #pragma unroll
    for (int i = 0; i < 4; i++)
        #pragma unroll
        for (int j = 0; j < 4; j++) acc2[i][j] = 0ull;

    #pragma unroll 1
    for (int kd = 0; kd < 7; kd++) {
        const float* plane = &smx[(ld + kd) * 1232];
        #pragma unroll
        for (int hr = 0; hr < 10; hr++) {
            const float* row = plane + (lh + hr) * 56 + w0;
            float r[16];
            *(float4*)&r[0]  = *(const float4*)&row[0];
            *(float4*)&r[4]  = *(const float4*)&row[4];
            *(float4*)&r[8]  = *(const float4*)&row[8];
            *(float4*)&r[12] = *(const float4*)&row[12];
            unsigned long long Pe[7], Po[6];
            #pragma unroll
            for (int j = 0; j < 7; j++) Pe[j] = pack2(r[2 * j], r[2 * j + 1]);
            #pragma unroll
            for (int j = 0; j < 6; j++) Po[j] = pack2(r[2 * j + 1], r[2 * j + 2]);
            #pragma unroll
            for (int oh = 0; oh < 4; oh++) {
                const int kh = hr - oh;
                if (kh >= 0 && kh < 7) {
                    const unsigned long long* wp =
                        (const unsigned long long*)&wgt2[kd * 49 + kh * 7];
                    #pragma unroll
                    for (int kw = 0; kw < 7; kw++) {
                        const unsigned long long b2 = wp[kw];
                        const int t = kw >> 1;
                        if (kw & 1) {
                            #pragma unroll
                            for (int j = 0; j < 4; j++) fma2(acc2[oh][j], Po[t + j], b2);
                        } else {
                            #pragma unroll
                            for (int j = 0; j < 4; j++) fma2(acc2[oh][j], Pe[t + j], b2);
                        }
                    }
                }
            }
        }
    }

    const float bsv = sbias;
    const int gd = d_t * 16 + ld;
    __nv_bfloat16* obase = g_hb + (size_t)(b * CH + c) * VOX + gd * 2304;
    #pragma unroll
    for (int oh = 0; oh < 4; oh++) {
        const int gh = h_t * 16 + lh + oh;
        float a[8];
        #pragma unroll
        for (int j = 0; j < 4; j++) { unpack2(acc2[oh][j], a[2 * j], a[2 * j + 1]); }
        unsigned uw[4];
        #pragma unroll
        for (int j = 0; j < 4; j++) {
            const __nv_bfloat162 p = __floats2bfloat162_rn(a[2 * j] + bsv, a[2 * j + 1] + bsv);
            uw[j] = *(const unsigned*)&p;
        }
        *(uint4*)(obase + gh * 48 + w0) = make_uint4(uw[0], uw[1], uw[2], uw[3]);
    }
}

/* ---------------- K2: channel LayerNorm + transpose to [v][c] bf16 ---------------- */
__global__ __launch_bounds__(256) void k_ln(const float* __restrict__ ln_w,
                                            const float* __restrict__ ln_b)
{
    const int b = blockIdx.y;
    const int v0 = blockIdx.x * 64;
    __shared__ float sm[96 * 65];
    __shared__ float ps[256], ps2[256];
    __shared__ float smean[64], srstd[64];

    const __nv_bfloat16* hin = g_hb + (size_t)b * CH * VOX;
    for (int i = threadIdx.x; i < 96 * 32; i += 256) {
        const int cc = i >> 5, p = i & 31;
        const float2 f = __bfloat1622float2(
            *(const __nv_bfloat162*)(hin + (size_t)cc * VOX + v0 + 2 * p));
        sm[cc * 65 + 2 * p]     = f.x;
        sm[cc * 65 + 2 * p + 1] = f.y;
    }
    __syncthreads();
    {
        const int vv = threadIdx.x & 63, q = threadIdx.x >> 6;
        float s1 = 0.f, s2 = 0.f;
        for (int cc = q * 24; cc < q * 24 + 24; cc++) {
            const float t = sm[cc * 65 + vv]; s1 += t; s2 += t * t;
        }
        ps[threadIdx.x] = s1; ps2[threadIdx.x] = s2;
    }
    __syncthreads();
    if (threadIdx.x < 64) {
        const float s1 = ps[threadIdx.x] + ps[threadIdx.x + 64] + ps[threadIdx.x + 128] + ps[threadIdx.x + 192];
        const float s2 = ps2[threadIdx.x] + ps2[threadIdx.x + 64] + ps2[threadIdx.x + 128] + ps2[threadIdx.x + 192];
        const float mean = s1 * (1.f / 96.f);
        const float var  = s2 * (1.f / 96.f) - mean * mean;
        smean[threadIdx.x] = mean;
        srstd[threadIdx.x] = rsqrtf(var + 1e-6f);
    }
    __syncthreads();
    __nv_bfloat16* outp = g_hn + (size_t)b * VOX * CH;
    for (int i = threadIdx.x; i < 64 * 48; i += 256) {
        const int vv = i / 48;
        const int cp = i - vv * 48;
        const int c0 = cp * 2;
        const float mean = smean[vv], rs = srstd[vv];
        const float a0 = (sm[c0 * 65 + vv]       - mean) * rs * ln_w[c0]     + ln_b[c0];
        const float a1 = (sm[(c0 + 1) * 65 + vv] - mean) * rs * ln_w[c0 + 1] + ln_b[c0 + 1];
        *(__nv_bfloat162*)(outp + (size_t)(v0 + vv) * CH + c0) = __floats2bfloat162_rn(a0, a1);
    }
}

/* ---------------- K3: FUSED pw1 + GELU + pw2 + residual ----------------
   Block = 128 voxels. 8 warps as 4(M)x2(N), warp tile 32x48.
   Loop kc=0..3 over 96-wide chunks of the 384 intermediate channels:
     gemm1 chunk -> bias+gelu -> smem bf16 -> gemm2 partial accumulate.
   Dynamic smem layout (bytes):
     As : [0, 26624)       128x104 bf16
     W1s: [26624, 46592)   96x104 bf16
     W2s: [46592, 66560)   96x104 bf16
     Ys : [66560, 93184)   128x104 bf16
     Cs : [0, 49152) float (after final sync, reuses As/W1s/part of W2s) */
__global__ __launch_bounds__(256) void k_gemm12(const float* __restrict__ x,
                                                const float* __restrict__ gamma,
                                                float* __restrict__ outg)
{
    const int vb = blockIdx.x * 128;
    const int b  = blockIdx.y;

    extern __shared__ __align__(16) char dsm[];
    __nv_bfloat16* As  = (__nv_bfloat16*)(dsm);
    __nv_bfloat16* W1s = (__nv_bfloat16*)(dsm + 26624);
    __nv_bfloat16* W2s = (__nv_bfloat16*)(dsm + 46592);
    __nv_bfloat16* Ys  = (__nv_bfloat16*)(dsm + 66560);
    float* Cs = (float*)dsm;

    __shared__ float sb1[96];
    __shared__ float sb2[96], sgam[96];

    const __nv_bfloat16* Ag  = g_hn + (size_t)b * VOX * CH;
    const __nv_bfloat16* W1g = g_W1h + b * CH4 * CH;
    const __nv_bfloat16* W2g = g_W2h + b * CH * CH4;
    const int tid = threadIdx.x;

    if (tid < 96) { sb2[tid] = g_b2[b * CH + tid]; sgam[tid] = gamma[tid]; }

    /* load A once: 128 rows x 96 cols bf16 */
    #pragma unroll
    for (int t = 0; t < 6; t++) {
        const int idx = tid + t * 256;
        const int row = idx / 12, q = idx % 12;
        *(uint4*)&As[row * 104 + q * 8] =
            *(const uint4*)(Ag + (size_t)(vb + row) * CH + q * 8);
    }

    const int w = tid >> 5, l = tid & 31;
    const int m0 = (w >> 1) * 32, n0 = (w & 1) * 48;
    const unsigned aBase  = (unsigned)__cvta_generic_to_shared(As);
    const unsigned w1Base = (unsigned)__cvta_generic_to_shared(W1s);
    const unsigned w2Base = (unsigned)__cvta_generic_to_shared(W2s);
    const unsigned yBase  = (unsigned)__cvta_generic_to_shared(Ys);

    const int arow = l & 15, ahalf = l >> 4;
    const int brow = l & 7, bhalf = (l >> 3) & 1, bsub = l >> 4;
    const int g = l >> 2, tig = l & 3;

    float acc2[2][6][4];
    #pragma unroll
    for (int i = 0; i < 2; i++)
        #pragma unroll
        for (int j = 0; j < 6; j++)
            #pragma unroll
            for (int q = 0; q < 4; q++) acc2[i][j][q] = 0.f;

    #pragma unroll 1
    for (int kc = 0; kc < 4; kc++) {
        /* load W1 chunk rows [kc*96, kc*96+96) x 96, W2 chunk rows 96 x k-slice,
           and bias1 chunk */
        #pragma unroll
        for (int t = 0; t < 5; t++) {
            const int idx = tid + t * 256;
            if (idx < 1152) {
                const int row = idx / 12, q = idx % 12;
                *(uint4*)&W1s[row * 104 + q * 8] =
                    *(const uint4*)(W1g + (kc * 96 + row) * CH + q * 8);
                *(uint4*)&W2s[row * 104 + q * 8] =
                    *(const uint4*)(W2g + row * CH4 + kc * 96 + q * 8);
            }
        }
        if (tid < 96) sb1[tid] = g_b1[b * CH4 + kc * 96 + tid];
        __syncthreads();

        /* gemm1 chunk: (128 x 96) = A(128x96) x W1c(96x96)^T, warp tile 32x48 */
        float acc1[2][6][4];
        #pragma unroll
        for (int i = 0; i < 2; i++)
            #pragma unroll
            for (int j = 0; j < 6; j++)
                #pragma unroll
                for (int q = 0; q < 4; q++) acc1[i][j][q] = 0.f;

        #pragma unroll
        for (int kk = 0; kk < 6; kk++) {
            unsigned a[2][4];
            #pragma unroll
            for (int i = 0; i < 2; i++) {
                const unsigned addr = aBase +
                    ((m0 + 16 * i + arow) * 104 + kk * 16 + ahalf * 8) * 2;
                ldsm_x4(a[i][0], a[i][1], a[i][2], a[i][3], addr);
            }
            unsigned bf[6][2];
            #pragma unroll
            for (int jb = 0; jb < 3; jb++) {
                const unsigned addr = w1Base +
                    ((n0 + 8 * (2 * jb + bsub) + brow) * 104 + kk * 16 + bhalf * 8) * 2;
                unsigned t0, t1, t2, t3;
                ldsm_x4(t0, t1, t2, t3, addr);
                bf[2 * jb][0] = t0; bf[2 * jb][1] = t1;
                bf[2 * jb + 1][0] = t2; bf[2 * jb + 1][1] = t3;
            }
            #pragma unroll
            for (int i = 0; i < 2; i++)
                #pragma unroll
                for (int j = 0; j < 6; j++)
                    mma16816(acc1[i][j], a[i], bf[j]);
        }

        /* bias + gelu -> Ys bf16 */
        #pragma unroll
        for (int i = 0; i < 2; i++) {
            #pragma unroll
            for (int j = 0; j < 6; j++) {
                const int colc = n0 + 8 * j + tig * 2;
                const float bs0 = sb1[colc], bs1 = sb1[colc + 1];
                const float v0 = gelu_fast(acc1[i][j][0] + bs0);
                const float v1 = gelu_fast(acc1[i][j][1] + bs1);
                const float v2 = gelu_fast(acc1[i][j][2] + bs0);
                const float v3 = gelu_fast(acc1[i][j][3] + bs1);
                const int r0 = m0 + 16 * i + g;
                *(__nv_bfloat162*)&Ys[r0 * 104 + colc]       = __floats2bfloat162_rn(v0, v1);
                *(__nv_bfloat162*)&Ys[(r0 + 8) * 104 + colc] = __floats2bfloat162_rn(v2, v3);
            }
        }
        __syncthreads();

        /* gemm2 partial: acc2 += Ys(128x96) x W2c(96x96)^T */
        #pragma unroll
        for (int kk = 0; kk < 6; kk++) {
            unsigned a[2][4];
            #pragma unroll
            for (int i = 0; i < 2; i++) {
                const unsigned addr = yBase +
                    ((m0 + 16 * i + arow) * 104 + kk * 16 + ahalf * 8) * 2;
                ldsm_x4(a[i][0], a[i][1], a[i][2], a[i][3], addr);
            }
            unsigned bf[6][2];
            #pragma unroll
            for (int jb = 0; jb < 3; jb++) {
                const unsigned addr = w2Base +
                    ((n0 + 8 * (2 * jb + bsub) + brow) * 104 + kk * 16 + bhalf * 8) * 2;
                unsigned t0, t1, t2, t3;
                ldsm_x4(t0, t1, t2, t3, addr);
                bf[2 * jb][0] = t0; bf[2 * jb][1] = t1;
                bf[2 * jb + 1][0] = t2; bf[2 * jb + 1][1] = t3;
            }
            #pragma unroll
            for (int i = 0; i < 2; i++)
                #pragma unroll
                for (int j = 0; j < 6; j++)
                    mma16816(acc2[i][j], a[i], bf[j]);
        }
        __syncthreads();
    }

    /* final epilogue: bias2 + residual through smem transpose */
    #pragma unroll
    for (int i = 0; i < 2; i++) {
        #pragma unroll
        for (int j = 0; j < 6; j++) {
            const int col = n0 + 8 * j + tig * 2;
            const int r0 = m0 + 16 * i + g;
            Cs[col * 128 + r0]           = acc2[i][j][0] + sb2[col];
            Cs[(col + 1) * 128 + r0]     = acc2[i][j][1] + sb2[col + 1];
            Cs[col * 128 + r0 + 8]       = acc2[i][j][2] + sb2[col];
            Cs[(col + 1) * 128 + r0 + 8] = acc2[i][j][3] + sb2[col + 1];
        }
    }
    __syncthreads();

    #pragma unroll
    for (int t = 0; t < 12; t++) {
        const int idx = tid + t * 256;
        const int row = idx >> 5, q = idx & 31;
        const size_t oidx = (size_t)(b * CH + row) * VOX + vb + q * 4;
        const float gm = sgam[row];
        const float4 xv = *(const float4*)(x + oidx);
        const float4 cv = *(const float4*)&Cs[row * 128 + q * 4];
        float4 res;
        res.x = xv.x + gm * cv.x;
        res.y = xv.y + gm * cv.y;
        res.z = xv.z + gm * cv.z;
        res.w = xv.w + gm * cv.w;
        *(float4*)(outg + oidx) = res;
    }
}

/* ---------------- launch ---------------- */
extern "C" void kernel_launch(void* const* d_in, const int* in_sizes, int n_in,
                              void* d_out, int out_size)
{
    const float* x            = (const float*)d_in[0];
    const float* s            = (const float*)d_in[1];
    const float* ln_w         = (const float*)d_in[2];
    const float* ln_b         = (const float*)d_in[3];
    const float* gamma        = (const float*)d_in[4];
    const float* dw_fc_w      = (const float*)d_in[5];
    const float* dw_fc_b      = (const float*)d_in[6];
    const float* dw_bank      = (const float*)d_in[7];
    const float* dw_bias_bank = (const float*)d_in[8];
    const float* pw1_fc_w     = (const float*)d_in[9];
    const float* pw1_fc_b     = (const float*)d_in[10];
    const float* pw1_bank     = (const float*)d_in[11];
    const float* pw1_bias_bank= (const float*)d_in[12];
    const float* pw2_fc_w     = (const float*)d_in[13];
    const float* pw2_fc_b     = (const float*)d_in[14];
    const float* pw2_bank     = (const float*)d_in[15];
    const float* pw2_bias_bank= (const float*)d_in[16];
    float* outp = (float*)d_out;

    const int dwSmem = 22 * 22 * 56 * 4;    /* 108416 B dynamic */
    cudaFuncSetAttribute(k_dwconv, cudaFuncAttributeMaxDynamicSharedMemorySize, dwSmem);
    const int fgSmem = 93184;
    cudaFuncSetAttribute(k_gemm12, cudaFuncAttributeMaxDynamicSharedMemorySize, fgSmem);

    k_weights<<<dim3(146, 3, NB), 256>>>(s,
        dw_fc_w, dw_fc_b, dw_bank, dw_bias_bank,
        pw1_fc_w, pw1_fc_b, pw1_bank, pw1_bias_bank,
        pw2_fc_w, pw2_fc_b, pw2_bank, pw2_bias_bank);

    k_dwconv<<<dim3(9, CH, NB), 384, dwSmem>>>(x);

    k_ln<<<dim3(VOX / 64, NB, 1), 256>>>(ln_w, ln_b);

    k_gemm12<<<dim3(VOX / 128, NB, 1), 256, fgSmem>>>(x, gamma, outp);
}

// round 6
// speedup vs baseline: 3.6221x; 1.1049x over previous
#include <cuda_runtime.h>
#include <cuda_bf16.h>

#define SPD   48
#define VOX   (48*48*48)      /* 110592 */
#define CH    96
#define CH4   384
#define LATD  8
#define STY   128
#define NB    2

/* ---------------- scratch (device globals; no allocation) ---------------- */
__device__ float g_wdw[NB * CH * 343];
__device__ float g_bdw[NB * CH];
__device__ __nv_bfloat16 g_W1h[NB * CH4 * CH];               /* pw1 weights bf16 [o][c] */
__device__ float g_b1[NB * CH4];
__device__ __nv_bfloat16 g_W2h[NB * CH * CH4];               /* pw2 weights bf16 [o][c4] */
__device__ float g_b2[NB * CH];
__device__ __nv_bfloat16 g_hb[(size_t)NB * CH * VOX];        /* dwconv out, [b][c][v] bf16 */

/* ---------------- helpers ---------------- */
__device__ __forceinline__ unsigned long long pack2(float lo, float hi) {
    unsigned long long r;
    asm("mov.b64 %0, {%1, %2};" : "=l"(r) : "f"(lo), "f"(hi));
    return r;
}
__device__ __forceinline__ void unpack2(unsigned long long v, float& lo, float& hi) {
    asm("mov.b64 {%0, %1}, %2;" : "=f"(lo), "=f"(hi) : "l"(v));
}
__device__ __forceinline__ void fma2(unsigned long long& d, unsigned long long a, unsigned long long b) {
    asm("fma.rn.f32x2 %0, %1, %2, %0;" : "+l"(d) : "l"(a), "l"(b));
}
__device__ __forceinline__ float gelu_fast(float x) {
    float u = 0.7978845608f * x * (1.0f + 0.044715f * x * x);
    float t;
    asm("tanh.approx.f32 %0, %1;" : "=f"(t) : "f"(u));
    return 0.5f * x * (1.0f + t);
}
__device__ __forceinline__ void ldsm_x4(unsigned& r0, unsigned& r1, unsigned& r2, unsigned& r3,
                                        unsigned addr) {
    asm volatile("ldmatrix.sync.aligned.m8n8.x4.shared.b16 {%0,%1,%2,%3}, [%4];"
                 : "=r"(r0), "=r"(r1), "=r"(r2), "=r"(r3) : "r"(addr));
}
__device__ __forceinline__ void mma16816(float* c, const unsigned* a, const unsigned* b) {
    asm volatile("mma.sync.aligned.m16n8k16.row.col.f32.bf16.bf16.f32 "
                 "{%0,%1,%2,%3}, {%4,%5,%6,%7}, {%8,%9}, {%0,%1,%2,%3};"
                 : "+f"(c[0]), "+f"(c[1]), "+f"(c[2]), "+f"(c[3])
                 : "r"(a[0]), "r"(a[1]), "r"(a[2]), "r"(a[3]), "r"(b[0]), "r"(b[1]));
}

/* ---------------- K0: hyper-weight materialization ---------------- */
__global__ void k_weights(const float* __restrict__ s,
    const float* __restrict__ dw_fc_w,  const float* __restrict__ dw_fc_b,
    const float* __restrict__ dw_bank,  const float* __restrict__ dw_bias_bank,
    const float* __restrict__ pw1_fc_w, const float* __restrict__ pw1_fc_b,
    const float* __restrict__ pw1_bank, const float* __restrict__ pw1_bias_bank,
    const float* __restrict__ pw2_fc_w, const float* __restrict__ pw2_fc_b,
    const float* __restrict__ pw2_bank, const float* __restrict__ pw2_bias_bank)
{
    const int stage = blockIdx.y;
    const int b = blockIdx.z;
    __shared__ float z[LATD];
    const float* fcw = (stage == 0) ? dw_fc_w : (stage == 1) ? pw1_fc_w : pw2_fc_w;
    const float* fcb = (stage == 0) ? dw_fc_b : (stage == 1) ? pw1_fc_b : pw2_fc_b;
    if (threadIdx.x < LATD) {
        float acc = fcb[threadIdx.x];
        for (int j = 0; j < STY; j++) acc += s[b * STY + j] * fcw[threadIdx.x * STY + j];
        z[threadIdx.x] = acc;
    }
    __syncthreads();
    const int idx = blockIdx.x * blockDim.x + threadIdx.x;
    if (stage == 0) {
        const int NW = CH * 343;
        if (idx < NW) {
            float a = 0.f;
            #pragma unroll
            for (int l = 0; l < LATD; l++) a += dw_bank[(size_t)idx * LATD + l] * z[l];
            g_wdw[b * NW + idx] = a;
        } else if (idx < NW + CH) {
            const int c = idx - NW; float a = 0.f;
            #pragma unroll
            for (int l = 0; l < LATD; l++) a += dw_bias_bank[c * LATD + l] * z[l];
            g_bdw[b * CH + c] = a;
        }
    } else if (stage == 1) {
        const int NW = CH4 * CH;
        if (idx < NW) {
            float a = 0.f;
            #pragma unroll
            for (int l = 0; l < LATD; l++) a += pw1_bank[(size_t)idx * LATD + l] * z[l];
            g_W1h[b * NW + idx] = __float2bfloat16(a);
        } else if (idx < NW + CH4) {
            const int o = idx - NW; float a = 0.f;
            #pragma unroll
            for (int l = 0; l < LATD; l++) a += pw1_bias_bank[o * LATD + l] * z[l];
            g_b1[b * CH4 + o] = a;
        }
    } else {
        const int NW = CH * CH4;
        if (idx < NW) {
            float a = 0.f;
            #pragma unroll
            for (int l = 0; l < LATD; l++) a += pw2_bank[(size_t)idx * LATD + l] * z[l];
            g_W2h[b * NW + idx] = __float2bfloat16(a);
        } else if (idx < NW + CH) {
            const int o = idx - NW; float a = 0.f;
            #pragma unroll
            for (int l = 0; l < LATD; l++) a += pw2_bias_bank[o * LATD + l] * z[l];
            g_b2[b * CH + o] = a;
        }
    }
}

/* ---------------- K1: depthwise 7^3 conv, row-sliding f32x2 ----------------
   Block: one (b,c), tile 16(d) x 16(h) x 48(w). 384 threads (12 warps), each
   8w x 4h outputs. Dynamic smem halo 22x22x56 fp32 (108 KB). */
__global__ __launch_bounds__(384) void k_dwconv(const float* __restrict__ x)
{
    const int d_t = blockIdx.x / 3, h_t = blockIdx.x % 3;
    const int c = blockIdx.y, b = blockIdx.z;

    extern __shared__ __align__(16) float smx[];        /* 22*22*56 = 108416 B */
    __shared__ __align__(8) float2 wgt2[343];
    __shared__ float sbias;

    const float* xin = x + (size_t)(b * CH + c) * VOX;
    for (int i = threadIdx.x; i < 343; i += 384) {
        const float wv = g_wdw[(b * CH + c) * 343 + i];
        wgt2[i] = make_float2(wv, wv);
    }
    if (threadIdx.x == 0) sbias = g_bdw[b * CH + c];

    const int d0 = d_t * 16 - 3, h0 = h_t * 16 - 3;
    for (int i = threadIdx.x; i < 22 * 22 * 56; i += 384) {
        const int dd = i / 1232;
        const int r  = i - dd * 1232;
        const int hh = r / 56;
        const int ww = r - hh * 56;
        const int gd = d0 + dd, gh = h0 + hh, gw = ww - 3;
        float v = 0.f;
        if ((unsigned)gd < 48u && (unsigned)gh < 48u && (unsigned)gw < 48u)
            v = xin[gd * 2304 + gh * 48 + gw];
        smx[i] = v;
    }
    __syncthreads();

    const int wseg = threadIdx.x % 6;
    const int rr   = threadIdx.x / 6;
    const int hseg = rr & 3;
    const int ld   = rr >> 2;
    const int w0 = wseg * 8, lh = hseg * 4;

    unsigned long long acc2[4][4];
    #pragma unroll
    for (int i = 0; i < 4; i++)
        #pragma unroll
        for (int j = 0; j < 4; j++) acc2[i][j] = 0ull;

    #pragma unroll 1
    for (int kd = 0; kd < 7; kd++) {
        const float* plane = &smx[(ld + kd) * 1232];
        #pragma unroll
        for (int hr = 0; hr < 10; hr++) {
            const float* row = plane + (lh + hr) * 56 + w0;
            float r[16];
            *(float4*)&r[0]  = *(const float4*)&row[0];
            *(float4*)&r[4]  = *(const float4*)&row[4];
            *(float4*)&r[8]  = *(const float4*)&row[8];
            *(float4*)&r[12] = *(const float4*)&row[12];
            unsigned long long Pe[7], Po[6];
            #pragma unroll
            for (int j = 0; j < 7; j++) Pe[j] = pack2(r[2 * j], r[2 * j + 1]);
            #pragma unroll
            for (int j = 0; j < 6; j++) Po[j] = pack2(r[2 * j + 1], r[2 * j + 2]);
            #pragma unroll
            for (int oh = 0; oh < 4; oh++) {
                const int kh = hr - oh;
                if (kh >= 0 && kh < 7) {
                    const unsigned long long* wp =
                        (const unsigned long long*)&wgt2[kd * 49 + kh * 7];
                    #pragma unroll
                    for (int kw = 0; kw < 7; kw++) {
                        const unsigned long long b2 = wp[kw];
                        const int t = kw >> 1;
                        if (kw & 1) {
                            #pragma unroll
                            for (int j = 0; j < 4; j++) fma2(acc2[oh][j], Po[t + j], b2);
                        } else {
                            #pragma unroll
                            for (int j = 0; j < 4; j++) fma2(acc2[oh][j], Pe[t + j], b2);
                        }
                    }
                }
            }
        }
    }

    const float bsv = sbias;
    const int gd = d_t * 16 + ld;
    __nv_bfloat16* obase = g_hb + (size_t)(b * CH + c) * VOX + gd * 2304;
    #pragma unroll
    for (int oh = 0; oh < 4; oh++) {
        const int gh = h_t * 16 + lh + oh;
        float a[8];
        #pragma unroll
        for (int j = 0; j < 4; j++) { unpack2(acc2[oh][j], a[2 * j], a[2 * j + 1]); }
        unsigned uw[4];
        #pragma unroll
        for (int j = 0; j < 4; j++) {
            const __nv_bfloat162 p = __floats2bfloat162_rn(a[2 * j] + bsv, a[2 * j + 1] + bsv);
            uw[j] = *(const unsigned*)&p;
        }
        *(uint4*)(obase + gh * 48 + w0) = make_uint4(uw[0], uw[1], uw[2], uw[3]);
    }
}

/* ---------------- gemm1 n-piece (template keeps acc1 live-range small) ---------------- */
template<int JB0, int NJB>
__device__ __forceinline__ void gemm1_piece(
    unsigned aBase, unsigned w1Base, const float* __restrict__ sb1,
    __nv_bfloat16* __restrict__ Ys,
    int m0, int n0, int arow, int ahalf, int brow, int bhalf, int bsub,
    int g, int tig)
{
    float acc1[2][2 * NJB][4];
    #pragma unroll
    for (int i = 0; i < 2; i++)
        #pragma unroll
        for (int j = 0; j < 2 * NJB; j++)
            #pragma unroll
            for (int q = 0; q < 4; q++) acc1[i][j][q] = 0.f;

    #pragma unroll
    for (int kk = 0; kk < 6; kk++) {
        unsigned a[2][4];
        #pragma unroll
        for (int i = 0; i < 2; i++) {
            const unsigned addr = aBase +
                ((m0 + 16 * i + arow) * 104 + kk * 16 + ahalf * 8) * 2;
            ldsm_x4(a[i][0], a[i][1], a[i][2], a[i][3], addr);
        }
        unsigned bf[2 * NJB][2];
        #pragma unroll
        for (int jb = 0; jb < NJB; jb++) {
            const unsigned addr = w1Base +
                ((n0 + 8 * (2 * (JB0 + jb) + bsub) + brow) * 104 + kk * 16 + bhalf * 8) * 2;
            unsigned t0, t1, t2, t3;
            ldsm_x4(t0, t1, t2, t3, addr);
            bf[2 * jb][0] = t0; bf[2 * jb][1] = t1;
            bf[2 * jb + 1][0] = t2; bf[2 * jb + 1][1] = t3;
        }
        #pragma unroll
        for (int i = 0; i < 2; i++)
            #pragma unroll
            for (int j = 0; j < 2 * NJB; j++)
                mma16816(acc1[i][j], a[i], bf[j]);
    }

    /* bias + gelu -> Ys bf16 */
    #pragma unroll
    for (int i = 0; i < 2; i++) {
        #pragma unroll
        for (int j = 0; j < 2 * NJB; j++) {
            const int colc = n0 + 8 * (2 * JB0 + j) + tig * 2;
            const float bs0 = sb1[colc], bs1 = sb1[colc + 1];
            const float v0 = gelu_fast(acc1[i][j][0] + bs0);
            const float v1 = gelu_fast(acc1[i][j][1] + bs1);
            const float v2 = gelu_fast(acc1[i][j][2] + bs0);
            const float v3 = gelu_fast(acc1[i][j][3] + bs1);
            const int r0 = m0 + 16 * i + g;
            *(__nv_bfloat162*)&Ys[r0 * 104 + colc]       = __floats2bfloat162_rn(v0, v1);
            *(__nv_bfloat162*)&Ys[(r0 + 8) * 104 + colc] = __floats2bfloat162_rn(v2, v3);
        }
    }
}

/* ---------------- K2: FUSED LN + pw1 + GELU + pw2 + residual ----------------
   Block = 128 voxels, 256 threads, 2 blocks/SM.
   Stage A: load raw dwconv tile g_hb[96][128] -> per-voxel LN -> As[v][c] bf16.
   Stage B: 4 chunks of 96 interm. channels: gemm1(+gelu) -> Ys -> gemm2 accum.
   Dynamic smem (93184 B):
     As : [0, 26624)       128x104 bf16
     W1s: [26624, 46592)   96x104 bf16
     W2s: [46592, 66560)   96x104 bf16
     Ys : [66560, 93184)   128x104 bf16  (aliased by Hs 96x136 bf16 in stage A)
     Cs : [0, 49152) float (epilogue, after final sync) */
__global__ __launch_bounds__(256, 2) void k_gemm12(const float* __restrict__ x,
                                                   const float* __restrict__ gamma,
                                                   const float* __restrict__ ln_w,
                                                   const float* __restrict__ ln_b,
                                                   float* __restrict__ outg)
{
    const int vb = blockIdx.x * 128;
    const int b  = blockIdx.y;

    extern __shared__ __align__(16) char dsm[];
    __nv_bfloat16* As  = (__nv_bfloat16*)(dsm);
    __nv_bfloat16* W1s = (__nv_bfloat16*)(dsm + 26624);
    __nv_bfloat16* W2s = (__nv_bfloat16*)(dsm + 46592);
    __nv_bfloat16* Ys  = (__nv_bfloat16*)(dsm + 66560);
    __nv_bfloat16* Hs  = (__nv_bfloat16*)(dsm + 66560);   /* alias (dead before Ys use) */
    float* Cs = (float*)dsm;

    __shared__ float sb1[96], sb2[96], sgam[96], snw[96], snb[96];
    __shared__ float ps1[256], psq[256];
    __shared__ float smean[128], srstd[128];

    const __nv_bfloat16* Hg  = g_hb + (size_t)b * CH * VOX;
    const __nv_bfloat16* W1g = g_W1h + b * CH4 * CH;
    const __nv_bfloat16* W2g = g_W2h + b * CH * CH4;
    const int tid = threadIdx.x;

    if (tid < 96) {
        sb2[tid] = g_b2[b * CH + tid];
        sgam[tid] = gamma[tid];
        snw[tid] = ln_w[tid];
        snb[tid] = ln_b[tid];
    }

    /* ---- Stage A: load H tile [96 ch][128 vox] ---- */
    #pragma unroll
    for (int t = 0; t < 6; t++) {
        const int idx = tid + t * 256;
        const int row = idx >> 4, q = idx & 15;
        *(uint4*)&Hs[row * 136 + q * 8] =
            *(const uint4*)(Hg + (size_t)row * VOX + vb + q * 8);
    }
    __syncthreads();

    {   /* per-voxel partial sums: thread t -> voxel t&127, channel-half t>>7 */
        const int v = tid & 127, c0 = (tid >> 7) * 48;
        float s1 = 0.f, s2 = 0.f;
        #pragma unroll
        for (int c = 0; c < 48; c++) {
            const float f = __bfloat162float(Hs[(c0 + c) * 136 + v]);
            s1 += f; s2 += f * f;
        }
        ps1[tid] = s1; psq[tid] = s2;
    }
    __syncthreads();
    if (tid < 128) {
        const float s1 = ps1[tid] + ps1[tid + 128];
        const float s2 = psq[tid] + psq[tid + 128];
        const float mean = s1 * (1.f / 96.f);
        const float var  = s2 * (1.f / 96.f) - mean * mean;
        smean[tid] = mean;
        srstd[tid] = rsqrtf(var + 1e-6f);
    }
    __syncthreads();
    {   /* normalize + transpose -> As[v][c] */
        const int v = tid & 127, c0 = (tid >> 7) * 48;
        const float mean = smean[v], rs = srstd[v];
        #pragma unroll
        for (int c = 0; c < 48; c += 2) {
            const float f0 = __bfloat162float(Hs[(c0 + c) * 136 + v]);
            const float f1 = __bfloat162float(Hs[(c0 + c + 1) * 136 + v]);
            const float a0 = (f0 - mean) * rs * snw[c0 + c]     + snb[c0 + c];
            const float a1 = (f1 - mean) * rs * snw[c0 + c + 1] + snb[c0 + c + 1];
            *(__nv_bfloat162*)&As[v * 104 + c0 + c] = __floats2bfloat162_rn(a0, a1);
        }
    }

    /* ---- Stage B: chunked fused GEMMs ---- */
    const int w = tid >> 5, l = tid & 31;
    const int m0 = (w >> 1) * 32, n0 = (w & 1) * 48;
    const unsigned aBase  = (unsigned)__cvta_generic_to_shared(As);
    const unsigned w1Base = (unsigned)__cvta_generic_to_shared(W1s);
    const unsigned w2Base = (unsigned)__cvta_generic_to_shared(W2s);
    const unsigned yBase  = (unsigned)__cvta_generic_to_shared(Ys);

    const int arow = l & 15, ahalf = l >> 4;
    const int brow = l & 7, bhalf = (l >> 3) & 1, bsub = l >> 4;
    const int g = l >> 2, tig = l & 3;

    float acc2[2][6][4];
    #pragma unroll
    for (int i = 0; i < 2; i++)
        #pragma unroll
        for (int j = 0; j < 6; j++)
            #pragma unroll
            for (int q = 0; q < 4; q++) acc2[i][j][q] = 0.f;

    #pragma unroll 1
    for (int kc = 0; kc < 4; kc++) {
        #pragma unroll
        for (int t = 0; t < 5; t++) {
            const int idx = tid + t * 256;
            if (idx < 1152) {
                const int row = idx / 12, q = idx % 12;
                *(uint4*)&W1s[row * 104 + q * 8] =
                    *(const uint4*)(W1g + (kc * 96 + row) * CH + q * 8);
                *(uint4*)&W2s[row * 104 + q * 8] =
                    *(const uint4*)(W2g + row * CH4 + kc * 96 + q * 8);
            }
        }
        if (tid < 96) sb1[tid] = g_b1[b * CH4 + kc * 96 + tid];
        __syncthreads();   /* also orders stage-A As writes / Hs reads vs Ys writes */

        /* gemm1 in two n-pieces to cap live registers */
        gemm1_piece<0, 2>(aBase, w1Base, sb1, Ys, m0, n0, arow, ahalf, brow, bhalf, bsub, g, tig);
        gemm1_piece<2, 1>(aBase, w1Base, sb1, Ys, m0, n0, arow, ahalf, brow, bhalf, bsub, g, tig);
        __syncthreads();

        /* gemm2 partial: acc2 += Ys(128x96) x W2c(96x96)^T */
        #pragma unroll
        for (int kk = 0; kk < 6; kk++) {
            unsigned a[2][4];
            #pragma unroll
            for (int i = 0; i < 2; i++) {
                const unsigned addr = yBase +
                    ((m0 + 16 * i + arow) * 104 + kk * 16 + ahalf * 8) * 2;
                ldsm_x4(a[i][0], a[i][1], a[i][2], a[i][3], addr);
            }
            unsigned bf[6][2];
            #pragma unroll
            for (int jb = 0; jb < 3; jb++) {
                const unsigned addr = w2Base +
                    ((n0 + 8 * (2 * jb + bsub) + brow) * 104 + kk * 16 + bhalf * 8) * 2;
                unsigned t0, t1, t2, t3;
                ldsm_x4(t0, t1, t2, t3, addr);
                bf[2 * jb][0] = t0; bf[2 * jb][1] = t1;
                bf[2 * jb + 1][0] = t2; bf[2 * jb + 1][1] = t3;
            }
            #pragma unroll
            for (int i = 0; i < 2; i++)
                #pragma unroll
                for (int j = 0; j < 6; j++)
                    mma16816(acc2[i][j], a[i], bf[j]);
        }
        __syncthreads();
    }

    /* final epilogue: bias2 + residual through smem transpose */
    #pragma unroll
    for (int i = 0; i < 2; i++) {
        #pragma unroll
        for (int j = 0; j < 6; j++) {
            const int col = n0 + 8 * j + tig * 2;
            const int r0 = m0 + 16 * i + g;
            Cs[col * 128 + r0]           = acc2[i][j][0] + sb2[col];
            Cs[(col + 1) * 128 + r0]     = acc2[i][j][1] + sb2[col + 1];
            Cs[col * 128 + r0 + 8]       = acc2[i][j][2] + sb2[col];
            Cs[(col + 1) * 128 + r0 + 8] = acc2[i][j][3] + sb2[col + 1];
        }
    }
    __syncthreads();

    #pragma unroll
    for (int t = 0; t < 12; t++) {
        const int idx = tid + t * 256;
        const int row = idx >> 5, q = idx & 31;
        const size_t oidx = (size_t)(b * CH + row) * VOX + vb + q * 4;
        const float gm = sgam[row];
        const float4 xv = *(const float4*)(x + oidx);
        const float4 cv = *(const float4*)&Cs[row * 128 + q * 4];
        float4 res;
        res.x = xv.x + gm * cv.x;
        res.y = xv.y + gm * cv.y;
        res.z = xv.z + gm * cv.z;
        res.w = xv.w + gm * cv.w;
        *(float4*)(outg + oidx) = res;
    }
}

/* ---------------- launch ---------------- */
extern "C" void kernel_launch(void* const* d_in, const int* in_sizes, int n_in,
                              void* d_out, int out_size)
{
    const float* x            = (const float*)d_in[0];
    const float* s            = (const float*)d_in[1];
    const float* ln_w         = (const float*)d_in[2];
    const float* ln_b         = (const float*)d_in[3];
    const float* gamma        = (const float*)d_in[4];
    const float* dw_fc_w      = (const float*)d_in[5];
    const float* dw_fc_b      = (const float*)d_in[6];
    const float* dw_bank      = (const float*)d_in[7];
    const float* dw_bias_bank = (const float*)d_in[8];
    const float* pw1_fc_w     = (const float*)d_in[9];
    const float* pw1_fc_b     = (const float*)d_in[10];
    const float* pw1_bank     = (const float*)d_in[11];
    const float* pw1_bias_bank= (const float*)d_in[12];
    const float* pw2_fc_w     = (const float*)d_in[13];
    const float* pw2_fc_b     = (const float*)d_in[14];
    const float* pw2_bank     = (const float*)d_in[15];
    const float* pw2_bias_bank= (const float*)d_in[16];
    float* outp = (float*)d_out;

    const int dwSmem = 22 * 22 * 56 * 4;    /* 108416 B dynamic */
    cudaFuncSetAttribute(k_dwconv, cudaFuncAttributeMaxDynamicSharedMemorySize, dwSmem);
    const int fgSmem = 93184;
    cudaFuncSetAttribute(k_gemm12, cudaFuncAttributeMaxDynamicSharedMemorySize, fgSmem);

    k_weights<<<dim3(146, 3, NB), 256>>>(s,
        dw_fc_w, dw_fc_b, dw_bank, dw_bias_bank,
        pw1_fc_w, pw1_fc_b, pw1_bank, pw1_bias_bank,
        pw2_fc_w, pw2_fc_b, pw2_bank, pw2_bias_bank);

    k_dwconv<<<dim3(9, CH, NB), 384, dwSmem>>>(x);

    k_gemm12<<<dim3(VOX / 128, NB, 1), 256, fgSmem>>>(x, gamma, ln_w, ln_b, outp);
}